// round 11
// baseline (speedup 1.0000x reference)
#include <cuda_runtime.h>
#include <cuda_fp16.h>
#include <math.h>

// ---------------- problem constants ----------------
#define MAX_NODES 50000
#define MAX_EDGES 600000
#define IN_CH 768
#define HID 128
#define REL_DIM 200
#define NUM_RELS 5

// ---------------- scratch (device globals) ----------------
__device__ float g_h[MAX_NODES * HID];
__device__ float g_wx[MAX_NODES * HID];
__device__ float g_agg[MAX_NODES * HID];
__device__ float g_sA[MAX_NODES];
__device__ float g_sB[MAX_NODES];
__device__ float g_relC[8];
__device__ int g_cnt[MAX_NODES];
__device__ int g_off[MAX_NODES + 1];
__device__ int g_cur[MAX_NODES];
__device__ int g_csr_src[MAX_EDGES];
__device__ int g_csr_et[MAX_EDGES];

static inline int cdiv(int a, int b) { return (a + b - 1) / b; }

__device__ __forceinline__ unsigned hpack(__half a, __half b) {
    unsigned short ua = *(unsigned short*)&a;
    unsigned short ub = *(unsigned short*)&b;
    return (unsigned)ua | ((unsigned)ub << 16);
}
__device__ __forceinline__ unsigned cvt2h(float x, float y) {
    return hpack(__float2half_rn(x), __float2half_rn(y));
}
__device__ __forceinline__ void split2h(float x, float y, unsigned& hi, unsigned& lo) {
    __half h0 = __float2half_rn(x), h1 = __float2half_rn(y);
    __half l0 = __float2half_rn(x - __half2float(h0));
    __half l1 = __float2half_rn(y - __half2float(h1));
    hi = hpack(h0, h1);
    lo = hpack(l0, l1);
}

// ---------------- HMMA fp16 GEMM (R7-proven version, DO NOT RESTRUCTURE) ------
// C[M,128] = A[M,K]fp32 @ B[128,K]fp32^T. A rounded fp16 in regs; B split hi/lo.
// C = A16*Bhi + A16*Blo, fp32 accum, err ~2^-12 rel. CTA 128x128, BK=32, 8 warps.
// blockIdx.y selects (B0->C0 with flags) or (B1->C1, flags=0).
#define F_BIASLEAKY 1
#define F_ROWDOT 2
#define GPAD 40

__device__ __forceinline__ void hmma16816(float* c, const unsigned* a, const unsigned* b) {
    asm volatile(
        "mma.sync.aligned.m16n8k16.row.col.f32.f16.f16.f32 "
        "{%0,%1,%2,%3}, {%4,%5,%6,%7}, {%8,%9}, {%0,%1,%2,%3};"
        : "+f"(c[0]), "+f"(c[1]), "+f"(c[2]), "+f"(c[3])
        : "r"(a[0]), "r"(a[1]), "r"(a[2]), "r"(a[3]), "r"(b[0]), "r"(b[1]));
}

__global__ __launch_bounds__(256, 2) void gemm_mma(
    const float* __restrict__ A, const float* __restrict__ B0,
    const float* __restrict__ bias, float* __restrict__ C0,
    const float* __restrict__ B1, float* __restrict__ C1,
    const float* __restrict__ avec, float* __restrict__ sA, float* __restrict__ sB,
    int M, int K, int flags0) {
    __shared__ __align__(16) __half As16[128 * GPAD];
    __shared__ __align__(16) __half Bhi[128 * GPAD];
    __shared__ __align__(16) __half Blo[128 * GPAD];
    __shared__ float s_red[2][128];

    const float* B = (blockIdx.y == 0) ? B0 : B1;
    float* C = (blockIdx.y == 0) ? C0 : C1;
    const int flags = (blockIdx.y == 0) ? flags0 : 0;

    const int tid = threadIdx.x;
    const int wid = tid >> 5;
    const int lane = tid & 31;
    const int wm = wid & 1;
    const int wn = wid >> 1;
    const int m0 = blockIdx.x * 128;
    const int g = lane >> 2;
    const int tq = lane & 3;

    float acc[4][4][4];
#pragma unroll
    for (int i = 0; i < 4; i++)
#pragma unroll
        for (int j = 0; j < 4; j++)
#pragma unroll
            for (int k = 0; k < 4; k++) acc[i][j][k] = 0.f;

    const int lrow = tid >> 1;
    const int lc0 = (tid & 1) << 4;
    const int gr = m0 + lrow;
    const float* aprow = A + (size_t)gr * K + lc0;
    const float* bprow = B + (size_t)lrow * K + lc0;

    float4 av[4], bv[4];
    // prologue: stage k-tile 0
#pragma unroll
    for (int q = 0; q < 4; q++) {
        av[q] = (gr < M) ? reinterpret_cast<const float4*>(aprow)[q]
                         : make_float4(0.f, 0.f, 0.f, 0.f);
        bv[q] = reinterpret_cast<const float4*>(bprow)[q];
    }

    const int nk = K >> 5;
    for (int it = 0; it < nk; it++) {
        __syncthreads();  // all warps done with smem from prev iter
        {
            unsigned ah[8];
#pragma unroll
            for (int q = 0; q < 4; q++) {
                ah[q * 2] = cvt2h(av[q].x, av[q].y);
                ah[q * 2 + 1] = cvt2h(av[q].z, av[q].w);
            }
            uint4* pa = reinterpret_cast<uint4*>(As16 + lrow * GPAD + lc0);
            pa[0] = make_uint4(ah[0], ah[1], ah[2], ah[3]);
            pa[1] = make_uint4(ah[4], ah[5], ah[6], ah[7]);
            unsigned h[8], l[8];
#pragma unroll
            for (int q = 0; q < 4; q++) {
                split2h(bv[q].x, bv[q].y, h[q * 2], l[q * 2]);
                split2h(bv[q].z, bv[q].w, h[q * 2 + 1], l[q * 2 + 1]);
            }
            uint4* qh = reinterpret_cast<uint4*>(Bhi + lrow * GPAD + lc0);
            uint4* ql = reinterpret_cast<uint4*>(Blo + lrow * GPAD + lc0);
            qh[0] = make_uint4(h[0], h[1], h[2], h[3]);
            qh[1] = make_uint4(h[4], h[5], h[6], h[7]);
            ql[0] = make_uint4(l[0], l[1], l[2], l[3]);
            ql[1] = make_uint4(l[4], l[5], l[6], l[7]);
        }
        __syncthreads();
        // stage next k-tile (overlaps with MMA below)
        if (it + 1 < nk) {
            const float* ap = aprow + (it + 1) * 32;
            const float* bp = bprow + (it + 1) * 32;
#pragma unroll
            for (int q = 0; q < 4; q++) {
                av[q] = (gr < M) ? reinterpret_cast<const float4*>(ap)[q]
                                 : make_float4(0.f, 0.f, 0.f, 0.f);
                bv[q] = reinterpret_cast<const float4*>(bp)[q];
            }
        }
#pragma unroll
        for (int ks = 0; ks < 2; ks++) {
            const int cc = ks * 16 + tq * 2;
            unsigned a[4][4], b0[4][2], b1[4][2];
#pragma unroll
            for (int nt = 0; nt < 4; nt++) {
                const int nb = wn * 32 + nt * 8 + g;
                b0[nt][0] = *reinterpret_cast<const unsigned*>(Bhi + nb * GPAD + cc);
                b0[nt][1] = *reinterpret_cast<const unsigned*>(Bhi + nb * GPAD + cc + 8);
                b1[nt][0] = *reinterpret_cast<const unsigned*>(Blo + nb * GPAD + cc);
                b1[nt][1] = *reinterpret_cast<const unsigned*>(Blo + nb * GPAD + cc + 8);
            }
#pragma unroll
            for (int mt = 0; mt < 4; mt++) {
                const int rb = wm * 64 + mt * 16 + g;
                a[mt][0] = *reinterpret_cast<const unsigned*>(As16 + rb * GPAD + cc);
                a[mt][1] = *reinterpret_cast<const unsigned*>(As16 + (rb + 8) * GPAD + cc);
                a[mt][2] = *reinterpret_cast<const unsigned*>(As16 + rb * GPAD + cc + 8);
                a[mt][3] = *reinterpret_cast<const unsigned*>(As16 + (rb + 8) * GPAD + cc + 8);
            }
#pragma unroll
            for (int mt = 0; mt < 4; mt++)
#pragma unroll
                for (int nt = 0; nt < 4; nt++) hmma16816(acc[mt][nt], a[mt], b0[nt]);
#pragma unroll
            for (int mt = 0; mt < 4; mt++)
#pragma unroll
                for (int nt = 0; nt < 4; nt++) hmma16816(acc[mt][nt], a[mt], b1[nt]);
        }
    }

    // ---------------- epilogue ----------------
    const bool dorow = (flags & F_ROWDOT) != 0;
    if (dorow) {
        if (tid < 128) { s_red[0][tid] = 0.f; s_red[1][tid] = 0.f; }
        __syncthreads();
    }
#pragma unroll
    for (int mt = 0; mt < 4; mt++) {
        float pa[2] = {0.f, 0.f}, pb[2] = {0.f, 0.f};
#pragma unroll
        for (int nt = 0; nt < 4; nt++) {
            const int c = wn * 32 + nt * 8 + tq * 2;
            float bi0 = 0.f, bi1 = 0.f;
            if (flags & F_BIASLEAKY) { bi0 = bias[c]; bi1 = bias[c + 1]; }
            float aA0 = 0.f, aA1 = 0.f, aB0 = 0.f, aB1 = 0.f;
            if (dorow) {
                aA0 = avec[c]; aA1 = avec[c + 1];
                aB0 = avec[128 + c]; aB1 = avec[128 + c + 1];
            }
#pragma unroll
            for (int half = 0; half < 2; half++) {
                const int r = m0 + wm * 64 + mt * 16 + g + half * 8;
                float v0 = acc[mt][nt][half * 2 + 0];
                float v1 = acc[mt][nt][half * 2 + 1];
                if (flags & F_BIASLEAKY) {
                    v0 += bi0; v1 += bi1;
                    v0 = v0 > 0.f ? v0 : 0.01f * v0;
                    v1 = v1 > 0.f ? v1 : 0.01f * v1;
                }
                if (dorow) {
                    pa[half] += v0 * aA0 + v1 * aA1;
                    pb[half] += v0 * aB0 + v1 * aB1;
                }
                if (r < M)
                    *reinterpret_cast<float2*>(C + (size_t)r * 128 + c) = make_float2(v0, v1);
            }
        }
        if (dorow) {
#pragma unroll
            for (int half = 0; half < 2; half++) {
                const int lr = wm * 64 + mt * 16 + g + half * 8;
                atomicAdd(&s_red[0][lr], pa[half]);
                atomicAdd(&s_red[1][lr], pb[half]);
            }
        }
    }
    if (dorow) {
        __syncthreads();
        if (tid < 128 && m0 + tid < M) {
            sA[m0 + tid] = s_red[0][tid];
            sB[m0 + tid] = s_red[1][tid];
        }
    }
}

// ---------------- relC[r] = (rel[r] @ Wr^T) . aC ----------------
__global__ __launch_bounds__(1024) void relc_kernel(const float* __restrict__ Wr,
                                                    const float* __restrict__ a,
                                                    const float* __restrict__ rel,
                                                    float* __restrict__ relC) {
    __shared__ float part[4 * REL_DIM];
    __shared__ float v[REL_DIM];
    const int tid = threadIdx.x;
    const int t = tid & 255;
    const int p = tid >> 8;
    if (t < REL_DIM) {
        float s = 0.f;
        const int h0 = p * 32;
#pragma unroll 8
        for (int h = 0; h < 32; h++) s += a[2 * HID + h0 + h] * Wr[(size_t)(h0 + h) * REL_DIM + t];
        part[p * REL_DIM + t] = s;
    }
    __syncthreads();
    if (tid < REL_DIM)
        v[tid] = part[tid] + part[REL_DIM + tid] + part[2 * REL_DIM + tid] + part[3 * REL_DIM + tid];
    __syncthreads();
    const int r = tid >> 5;
    const int lane = tid & 31;
    if (r < NUM_RELS) {
        float s = 0.f;
        for (int k = lane; k < REL_DIM; k += 32) s += rel[r * REL_DIM + k] * v[k];
#pragma unroll
        for (int o = 16; o; o >>= 1) s += __shfl_xor_sync(0xFFFFFFFFu, s, o);
        if (lane == 0) relC[r] = s;
    }
}

// ---------------- CSR build (by dst) ----------------
__global__ void count_kernel(const int* __restrict__ dst, int* __restrict__ cnt, int E) {
    const int e = blockIdx.x * blockDim.x + threadIdx.x;
    if (e < E) atomicAdd(cnt + dst[e], 1);
}

__global__ __launch_bounds__(1024) void scan_kernel(const int* __restrict__ cnt,
                                                    int* __restrict__ off,
                                                    int* __restrict__ cur, int N, int E) {
    __shared__ int part[1024];
    const int tid = threadIdx.x;
    const int chunk = (N + 1023) >> 10;
    const int s0 = tid * chunk;
    int s = 0;
    for (int i = 0; i < chunk; i++) {
        const int idx = s0 + i;
        if (idx < N) s += cnt[idx];
    }
    part[tid] = s;
    __syncthreads();
    for (int o = 1; o < 1024; o <<= 1) {
        int t = (tid >= o) ? part[tid - o] : 0;
        __syncthreads();
        part[tid] += t;
        __syncthreads();
    }
    int run = part[tid] - s;  // exclusive base
    for (int i = 0; i < chunk; i++) {
        const int idx = s0 + i;
        if (idx < N) {
            off[idx] = run;
            cur[idx] = run;
            run += cnt[idx];
        }
    }
    if (tid == 0) off[N] = E;
}

__global__ void fill_kernel(const int* __restrict__ src, const int* __restrict__ dst,
                            const int* __restrict__ et, int* __restrict__ cur,
                            int* __restrict__ csr_src, int* __restrict__ csr_et, int E) {
    const int e = blockIdx.x * blockDim.x + threadIdx.x;
    if (e >= E) return;
    const int pos = atomicAdd(cur + dst[e], 1);
    csr_src[pos] = src[e];
    csr_et[pos] = et[e];
}

// ---------------- fused per-dst attention: softmax + aggregate + residual + elu(+norm)
// warp per dst; gather unrolled 4x for MLP=4 against L2 latency.
__global__ void dst_fused_kernel(const float* __restrict__ wx, const float* __restrict__ res,
                                 const float* __restrict__ sA, const float* __restrict__ sB,
                                 const float* __restrict__ relC, const int* __restrict__ off,
                                 const int* __restrict__ csr_src, const int* __restrict__ csr_et,
                                 float* __restrict__ hout, int N, int fin) {
    const int d = (blockIdx.x * blockDim.x + threadIdx.x) >> 5;
    if (d >= N) return;
    const int lane = threadIdx.x & 31;
    const int rs = off[d];
    const int re = off[d + 1];
    const float sAd = sA[d];

    float4 acc = make_float4(0.f, 0.f, 0.f, 0.f);
    float psum = 0.f;
    for (int j0 = rs; j0 < re; j0 += 32) {
        const int j = j0 + lane;
        float p = 0.f;
        int s = 0;
        if (j < re) {
            s = csr_src[j];
            const int t = csr_et[j];
            float sc = sAd + sB[s] + relC[t];
            sc = sc > 0.f ? sc : 0.2f * sc;
            p = __expf(sc);
        }
        psum += p;
        const int cnt = min(32, re - j0);
        int k = 0;
        // unroll 4: four independent row gathers in flight (MLP=4)
        for (; k + 4 <= cnt; k += 4) {
            float pk0 = __shfl_sync(0xFFFFFFFFu, p, k);
            float pk1 = __shfl_sync(0xFFFFFFFFu, p, k + 1);
            float pk2 = __shfl_sync(0xFFFFFFFFu, p, k + 2);
            float pk3 = __shfl_sync(0xFFFFFFFFu, p, k + 3);
            int sk0 = __shfl_sync(0xFFFFFFFFu, s, k);
            int sk1 = __shfl_sync(0xFFFFFFFFu, s, k + 1);
            int sk2 = __shfl_sync(0xFFFFFFFFu, s, k + 2);
            int sk3 = __shfl_sync(0xFFFFFFFFu, s, k + 3);
            float4 v0 = reinterpret_cast<const float4*>(wx + (size_t)sk0 * 128)[lane];
            float4 v1 = reinterpret_cast<const float4*>(wx + (size_t)sk1 * 128)[lane];
            float4 v2 = reinterpret_cast<const float4*>(wx + (size_t)sk2 * 128)[lane];
            float4 v3 = reinterpret_cast<const float4*>(wx + (size_t)sk3 * 128)[lane];
            acc.x += v0.x * pk0; acc.y += v0.y * pk0; acc.z += v0.z * pk0; acc.w += v0.w * pk0;
            acc.x += v1.x * pk1; acc.y += v1.y * pk1; acc.z += v1.z * pk1; acc.w += v1.w * pk1;
            acc.x += v2.x * pk2; acc.y += v2.y * pk2; acc.z += v2.z * pk2; acc.w += v2.w * pk2;
            acc.x += v3.x * pk3; acc.y += v3.y * pk3; acc.z += v3.z * pk3; acc.w += v3.w * pk3;
        }
        for (; k < cnt; k++) {
            const float pk = __shfl_sync(0xFFFFFFFFu, p, k);
            const int sk = __shfl_sync(0xFFFFFFFFu, s, k);
            const float4 v = reinterpret_cast<const float4*>(wx + (size_t)sk * 128)[lane];
            acc.x += v.x * pk;
            acc.y += v.y * pk;
            acc.z += v.z * pk;
            acc.w += v.w * pk;
        }
    }
#pragma unroll
    for (int o = 16; o; o >>= 1) psum += __shfl_xor_sync(0xFFFFFFFFu, psum, o);
    const float inv = psum > 0.f ? 1.f / psum : 0.f;

    const float4 r = reinterpret_cast<const float4*>(res + (size_t)d * 128)[lane];
    float4 v;
    v.x = acc.x * inv + r.x;
    v.y = acc.y * inv + r.y;
    v.z = acc.z * inv + r.z;
    v.w = acc.w * inv + r.w;
    v.x = v.x > 0.f ? v.x : __expf(v.x) - 1.f;
    v.y = v.y > 0.f ? v.y : __expf(v.y) - 1.f;
    v.z = v.z > 0.f ? v.z : __expf(v.z) - 1.f;
    v.w = v.w > 0.f ? v.w : __expf(v.w) - 1.f;
    if (fin) {
        float ss = v.x * v.x + v.y * v.y + v.z * v.z + v.w * v.w;
#pragma unroll
        for (int o = 16; o; o >>= 1) ss += __shfl_xor_sync(0xFFFFFFFFu, ss, o);
        const float nrm = 1.f / fmaxf(sqrtf(ss), 1e-12f);
        v.x *= nrm; v.y *= nrm; v.z *= nrm; v.w *= nrm;
    }
    reinterpret_cast<float4*>(hout + (size_t)d * 128)[lane] = v;
}

// ---------------- launch ----------------
extern "C" void kernel_launch(void* const* d_in, const int* in_sizes, int n_in,
                              void* d_out, int out_size) {
    const float* x = (const float*)d_in[0];
    const int* ei = (const int*)d_in[1];
    const int* et = (const int*)d_in[2];
    const float* l1W = (const float*)d_in[3];
    const float* l1b = (const float*)d_in[4];
    const float* l2W = (const float*)d_in[5];
    const float* l2b = (const float*)d_in[6];
    const float* W1 = (const float*)d_in[7];
    const float* Wr1 = (const float*)d_in[8];
    const float* a1 = (const float*)d_in[9];
    const float* Wres1 = (const float*)d_in[10];
    const float* rel1 = (const float*)d_in[11];
    const float* W2 = (const float*)d_in[12];
    const float* Wr2 = (const float*)d_in[13];
    const float* a2 = (const float*)d_in[14];
    const float* Wres2 = (const float*)d_in[15];
    const float* rel2 = (const float*)d_in[16];

    const int N = in_sizes[0] / IN_CH;
    const int E = in_sizes[2];
    const int* src = ei;
    const int* dst = ei + E;

    float *h, *wx, *agg, *sA, *sB, *relC;
    int *cnt, *off, *cur, *csr_src, *csr_et;
    cudaGetSymbolAddress((void**)&h, g_h);
    cudaGetSymbolAddress((void**)&wx, g_wx);
    cudaGetSymbolAddress((void**)&agg, g_agg);
    cudaGetSymbolAddress((void**)&sA, g_sA);
    cudaGetSymbolAddress((void**)&sB, g_sB);
    cudaGetSymbolAddress((void**)&relC, g_relC);
    cudaGetSymbolAddress((void**)&cnt, g_cnt);
    cudaGetSymbolAddress((void**)&off, g_off);
    cudaGetSymbolAddress((void**)&cur, g_cur);
    cudaGetSymbolAddress((void**)&csr_src, g_csr_src);
    cudaGetSymbolAddress((void**)&csr_et, g_csr_et);

    const dim3 gGemm1(cdiv(N, 128), 1);
    const dim3 gGemm2(cdiv(N, 128), 2);
    const int gNodeWarp = cdiv(N, 8);
    const int gEdge = cdiv(E, 256);

    // CSR build (once per launch; graph shared by both layers)
    cudaMemsetAsync(cnt, 0, N * sizeof(int));
    count_kernel<<<gEdge, 256>>>(dst, cnt, E);
    scan_kernel<<<1, 1024>>>(cnt, off, cur, N, E);
    fill_kernel<<<gEdge, 256>>>(src, dst, et, cur, csr_src, csr_et, E);

    // layer 0: h = leaky_relu(x @ l1W^T + b, 0.01)
    gemm_mma<<<gGemm1, 256>>>(x, l1W, l1b, h, nullptr, nullptr, nullptr, nullptr, nullptr,
                              N, IN_CH, F_BIASLEAKY);

    const float* Ws[2] = {W1, W2};
    const float* Wrs[2] = {Wr1, Wr2};
    const float* as[2] = {a1, a2};
    const float* Wress[2] = {Wres1, Wres2};
    const float* rels[2] = {rel1, rel2};

    for (int l = 0; l < 2; l++) {
        relc_kernel<<<1, 1024>>>(Wrs[l], as[l], rels[l], relC);
        // y=0: wx = h@W^T (+rowdot -> sA,sB); y=1: agg = h@Wres^T (residual)
        gemm_mma<<<gGemm2, 256>>>(h, Ws[l], nullptr, wx, Wress[l], agg, as[l], sA, sB,
                                  N, HID, F_ROWDOT);
        dst_fused_kernel<<<gNodeWarp, 256>>>(wx, agg, sA, sB, relC, off, csr_src, csr_et,
                                             h, N, l == 1 ? 1 : 0);
    }

    // final: out = leaky_relu(h @ l2W^T + l2b, 0.01)
    gemm_mma<<<gGemm1, 256>>>(h, l2W, l2b, (float*)d_out, nullptr, nullptr, nullptr, nullptr,
                              nullptr, N, HID, F_BIASLEAKY);
}

// round 12
// speedup vs baseline: 1.4581x; 1.4581x over previous
#include <cuda_runtime.h>
#include <cuda_fp16.h>
#include <math.h>

// ---------------- problem constants ----------------
#define MAX_NODES 50000
#define MAX_EDGES 600000
#define IN_CH 768
#define HID 128
#define REL_DIM 200
#define NUM_RELS 5

// ---------------- scratch (device globals) ----------------
__device__ float g_h[MAX_NODES * HID];
__device__ float g_wx[MAX_NODES * HID];
__device__ float g_agg[MAX_NODES * HID];
__device__ float g_sA[MAX_NODES];
__device__ float g_sB[MAX_NODES];
__device__ float g_relC[8];
__device__ int g_cnt[MAX_NODES];
__device__ int g_off[MAX_NODES + 1];
__device__ int g_cur[MAX_NODES];
__device__ int g_csr_src[MAX_EDGES];
__device__ int g_csr_et[MAX_EDGES];

static inline int cdiv(int a, int b) { return (a + b - 1) / b; }

__device__ __forceinline__ unsigned hpack(__half a, __half b) {
    unsigned short ua = *(unsigned short*)&a;
    unsigned short ub = *(unsigned short*)&b;
    return (unsigned)ua | ((unsigned)ub << 16);
}
__device__ __forceinline__ unsigned cvt2h(float x, float y) {
    return hpack(__float2half_rn(x), __float2half_rn(y));
}
__device__ __forceinline__ void split2h(float x, float y, unsigned& hi, unsigned& lo) {
    __half h0 = __float2half_rn(x), h1 = __float2half_rn(y);
    __half l0 = __float2half_rn(x - __half2float(h0));
    __half l1 = __float2half_rn(y - __half2float(h1));
    hi = hpack(h0, h1);
    lo = hpack(l0, l1);
}

// ---------------- HMMA fp16 GEMM (pipelined): C[M,128] = A[M,K] @ B[128,K]^T ----
// A rounded to fp16 once; B split to fp16 hi/lo. C = A16*Bhi + A16*Blo.
// Error ~2^-12 relative (dropped A residual). CTA tile 128x128, BK=32, 8 warps.
// blockIdx.y selects (B0->C0 with flags) or (B1->C1, flags=0).
#define F_BIASLEAKY 1
#define F_ROWDOT 2
#define GPAD 40

__device__ __forceinline__ void hmma16816(float* c, const unsigned* a, const unsigned* b) {
    asm volatile(
        "mma.sync.aligned.m16n8k16.row.col.f32.f16.f16.f32 "
        "{%0,%1,%2,%3}, {%4,%5,%6,%7}, {%8,%9}, {%0,%1,%2,%3};"
        : "+f"(c[0]), "+f"(c[1]), "+f"(c[2]), "+f"(c[3])
        : "r"(a[0]), "r"(a[1]), "r"(a[2]), "r"(a[3]), "r"(b[0]), "r"(b[1]));
}

__global__ __launch_bounds__(256, 2) void gemm_mma(
    const float* __restrict__ A, const float* __restrict__ B0,
    const float* __restrict__ bias, float* __restrict__ C0,
    const float* __restrict__ B1, float* __restrict__ C1,
    const float* __restrict__ avec, float* __restrict__ sA, float* __restrict__ sB,
    int M, int K, int flags0) {
    __shared__ __align__(16) __half As16[128 * GPAD];
    __shared__ __align__(16) __half Bhi[128 * GPAD];
    __shared__ __align__(16) __half Blo[128 * GPAD];
    __shared__ float s_red[2][128];

    const float* B = (blockIdx.y == 0) ? B0 : B1;
    float* C = (blockIdx.y == 0) ? C0 : C1;
    const int flags = (blockIdx.y == 0) ? flags0 : 0;

    const int tid = threadIdx.x;
    const int wid = tid >> 5;
    const int lane = tid & 31;
    const int wm = wid & 1;
    const int wn = wid >> 1;
    const int m0 = blockIdx.x * 128;
    const int g = lane >> 2;
    const int tq = lane & 3;

    float acc[4][4][4];
#pragma unroll
    for (int i = 0; i < 4; i++)
#pragma unroll
        for (int j = 0; j < 4; j++)
#pragma unroll
            for (int k = 0; k < 4; k++) acc[i][j][k] = 0.f;

    const int lrow = tid >> 1;
    const int lc0 = (tid & 1) << 4;
    const int gr = m0 + lrow;
    const float* aprow = A + (size_t)gr * K + lc0;
    const float* bprow = B + (size_t)lrow * K + lc0;

    float4 av[4], bv[4];
    // prologue: stage k-tile 0
#pragma unroll
    for (int q = 0; q < 4; q++) {
        av[q] = (gr < M) ? reinterpret_cast<const float4*>(aprow)[q]
                         : make_float4(0.f, 0.f, 0.f, 0.f);
        bv[q] = reinterpret_cast<const float4*>(bprow)[q];
    }

    const int nk = K >> 5;
    for (int it = 0; it < nk; it++) {
        __syncthreads();  // all warps done with smem from prev iter
        {
            // A: single fp16 round
            unsigned ah[8];
#pragma unroll
            for (int q = 0; q < 4; q++) {
                ah[q * 2] = cvt2h(av[q].x, av[q].y);
                ah[q * 2 + 1] = cvt2h(av[q].z, av[q].w);
            }
            uint4* pa = reinterpret_cast<uint4*>(As16 + lrow * GPAD + lc0);
            pa[0] = make_uint4(ah[0], ah[1], ah[2], ah[3]);
            pa[1] = make_uint4(ah[4], ah[5], ah[6], ah[7]);
            // B: fp16 hi/lo split
            unsigned h[8], l[8];
#pragma unroll
            for (int q = 0; q < 4; q++) {
                split2h(bv[q].x, bv[q].y, h[q * 2], l[q * 2]);
                split2h(bv[q].z, bv[q].w, h[q * 2 + 1], l[q * 2 + 1]);
            }
            uint4* qh = reinterpret_cast<uint4*>(Bhi + lrow * GPAD + lc0);
            uint4* ql = reinterpret_cast<uint4*>(Blo + lrow * GPAD + lc0);
            qh[0] = make_uint4(h[0], h[1], h[2], h[3]);
            qh[1] = make_uint4(h[4], h[5], h[6], h[7]);
            ql[0] = make_uint4(l[0], l[1], l[2], l[3]);
            ql[1] = make_uint4(l[4], l[5], l[6], l[7]);
        }
        __syncthreads();
        // stage next k-tile (overlaps with MMA below)
        if (it + 1 < nk) {
            const float* ap = aprow + (it + 1) * 32;
            const float* bp = bprow + (it + 1) * 32;
#pragma unroll
            for (int q = 0; q < 4; q++) {
                av[q] = (gr < M) ? reinterpret_cast<const float4*>(ap)[q]
                                 : make_float4(0.f, 0.f, 0.f, 0.f);
                bv[q] = reinterpret_cast<const float4*>(bp)[q];
            }
        }
#pragma unroll
        for (int ks = 0; ks < 2; ks++) {
            const int cc = ks * 16 + tq * 2;
            unsigned a[4][4], b0[4][2], b1[4][2];
#pragma unroll
            for (int nt = 0; nt < 4; nt++) {
                const int nb = wn * 32 + nt * 8 + g;
                b0[nt][0] = *reinterpret_cast<const unsigned*>(Bhi + nb * GPAD + cc);
                b0[nt][1] = *reinterpret_cast<const unsigned*>(Bhi + nb * GPAD + cc + 8);
                b1[nt][0] = *reinterpret_cast<const unsigned*>(Blo + nb * GPAD + cc);
                b1[nt][1] = *reinterpret_cast<const unsigned*>(Blo + nb * GPAD + cc + 8);
            }
#pragma unroll
            for (int mt = 0; mt < 4; mt++) {
                const int rb = wm * 64 + mt * 16 + g;
                a[mt][0] = *reinterpret_cast<const unsigned*>(As16 + rb * GPAD + cc);
                a[mt][1] = *reinterpret_cast<const unsigned*>(As16 + (rb + 8) * GPAD + cc);
                a[mt][2] = *reinterpret_cast<const unsigned*>(As16 + rb * GPAD + cc + 8);
                a[mt][3] = *reinterpret_cast<const unsigned*>(As16 + (rb + 8) * GPAD + cc + 8);
            }
#pragma unroll
            for (int mt = 0; mt < 4; mt++)
#pragma unroll
                for (int nt = 0; nt < 4; nt++) hmma16816(acc[mt][nt], a[mt], b0[nt]);
#pragma unroll
            for (int mt = 0; mt < 4; mt++)
#pragma unroll
                for (int nt = 0; nt < 4; nt++) hmma16816(acc[mt][nt], a[mt], b1[nt]);
        }
    }

    // ---------------- epilogue ----------------
    const bool dorow = (flags & F_ROWDOT) != 0;
    if (dorow) {
        if (tid < 128) { s_red[0][tid] = 0.f; s_red[1][tid] = 0.f; }
        __syncthreads();
    }
#pragma unroll
    for (int mt = 0; mt < 4; mt++) {
        float pa[2] = {0.f, 0.f}, pb[2] = {0.f, 0.f};
#pragma unroll
        for (int nt = 0; nt < 4; nt++) {
            const int c = wn * 32 + nt * 8 + tq * 2;
            float bi0 = 0.f, bi1 = 0.f;
            if (flags & F_BIASLEAKY) { bi0 = bias[c]; bi1 = bias[c + 1]; }
            float aA0 = 0.f, aA1 = 0.f, aB0 = 0.f, aB1 = 0.f;
            if (dorow) {
                aA0 = avec[c]; aA1 = avec[c + 1];
                aB0 = avec[128 + c]; aB1 = avec[128 + c + 1];
            }
#pragma unroll
            for (int half = 0; half < 2; half++) {
                const int r = m0 + wm * 64 + mt * 16 + g + half * 8;
                float v0 = acc[mt][nt][half * 2 + 0];
                float v1 = acc[mt][nt][half * 2 + 1];
                if (flags & F_BIASLEAKY) {
                    v0 += bi0; v1 += bi1;
                    v0 = v0 > 0.f ? v0 : 0.01f * v0;
                    v1 = v1 > 0.f ? v1 : 0.01f * v1;
                }
                if (dorow) {
                    pa[half] += v0 * aA0 + v1 * aA1;
                    pb[half] += v0 * aB0 + v1 * aB1;
                }
                if (r < M)
                    *reinterpret_cast<float2*>(C + (size_t)r * 128 + c) = make_float2(v0, v1);
            }
        }
        if (dorow) {
#pragma unroll
            for (int half = 0; half < 2; half++) {
                const int lr = wm * 64 + mt * 16 + g + half * 8;
                atomicAdd(&s_red[0][lr], pa[half]);
                atomicAdd(&s_red[1][lr], pb[half]);
            }
        }
    }
    if (dorow) {
        __syncthreads();
        if (tid < 128 && m0 + tid < M) {
            sA[m0 + tid] = s_red[0][tid];
            sB[m0 + tid] = s_red[1][tid];
        }
    }
}

// ---------------- relC[r] = (rel[r] @ Wr^T) . aC ----------------
__global__ __launch_bounds__(1024) void relc_kernel(const float* __restrict__ Wr,
                                                    const float* __restrict__ a,
                                                    const float* __restrict__ rel,
                                                    float* __restrict__ relC) {
    __shared__ float part[4 * REL_DIM];
    __shared__ float v[REL_DIM];
    const int tid = threadIdx.x;
    const int t = tid & 255;
    const int p = tid >> 8;
    if (t < REL_DIM) {
        float s = 0.f;
        const int h0 = p * 32;
#pragma unroll 8
        for (int h = 0; h < 32; h++) s += a[2 * HID + h0 + h] * Wr[(size_t)(h0 + h) * REL_DIM + t];
        part[p * REL_DIM + t] = s;
    }
    __syncthreads();
    if (tid < REL_DIM)
        v[tid] = part[tid] + part[REL_DIM + tid] + part[2 * REL_DIM + tid] + part[3 * REL_DIM + tid];
    __syncthreads();
    const int r = tid >> 5;
    const int lane = tid & 31;
    if (r < NUM_RELS) {
        float s = 0.f;
        for (int k = lane; k < REL_DIM; k += 32) s += rel[r * REL_DIM + k] * v[k];
#pragma unroll
        for (int o = 16; o; o >>= 1) s += __shfl_xor_sync(0xFFFFFFFFu, s, o);
        if (lane == 0) relC[r] = s;
    }
}

// ---------------- CSR build (by dst) ----------------
__global__ void count_kernel(const int* __restrict__ dst, int* __restrict__ cnt, int E) {
    const int e = blockIdx.x * blockDim.x + threadIdx.x;
    if (e < E) atomicAdd(cnt + dst[e], 1);
}

__global__ __launch_bounds__(1024) void scan_kernel(const int* __restrict__ cnt,
                                                    int* __restrict__ off,
                                                    int* __restrict__ cur, int N, int E) {
    __shared__ int part[1024];
    const int tid = threadIdx.x;
    const int chunk = (N + 1023) >> 10;
    const int s0 = tid * chunk;
    int s = 0;
    for (int i = 0; i < chunk; i++) {
        const int idx = s0 + i;
        if (idx < N) s += cnt[idx];
    }
    part[tid] = s;
    __syncthreads();
    for (int o = 1; o < 1024; o <<= 1) {
        int t = (tid >= o) ? part[tid - o] : 0;
        __syncthreads();
        part[tid] += t;
        __syncthreads();
    }
    int run = part[tid] - s;  // exclusive base
    for (int i = 0; i < chunk; i++) {
        const int idx = s0 + i;
        if (idx < N) {
            off[idx] = run;
            cur[idx] = run;
            run += cnt[idx];
        }
    }
    if (tid == 0) off[N] = E;
}

__global__ void fill_kernel(const int* __restrict__ src, const int* __restrict__ dst,
                            const int* __restrict__ et, int* __restrict__ cur,
                            int* __restrict__ csr_src, int* __restrict__ csr_et, int E) {
    const int e = blockIdx.x * blockDim.x + threadIdx.x;
    if (e >= E) return;
    const int pos = atomicAdd(cur + dst[e], 1);
    csr_src[pos] = src[e];
    csr_et[pos] = et[e];
}

// ---------------- fused per-dst attention: softmax + aggregate + residual + elu(+norm)
__global__ void dst_fused_kernel(const float* __restrict__ wx, const float* __restrict__ res,
                                 const float* __restrict__ sA, const float* __restrict__ sB,
                                 const float* __restrict__ relC, const int* __restrict__ off,
                                 const int* __restrict__ csr_src, const int* __restrict__ csr_et,
                                 float* __restrict__ hout, int N, int fin) {
    const int d = (blockIdx.x * blockDim.x + threadIdx.x) >> 5;
    if (d >= N) return;
    const int lane = threadIdx.x & 31;
    const int rs = off[d];
    const int re = off[d + 1];
    const float sAd = sA[d];

    float4 acc = make_float4(0.f, 0.f, 0.f, 0.f);
    float psum = 0.f;
    for (int j0 = rs; j0 < re; j0 += 32) {
        const int j = j0 + lane;
        float p = 0.f;
        int s = 0;
        if (j < re) {
            s = csr_src[j];
            const int t = csr_et[j];
            float sc = sAd + sB[s] + relC[t];
            sc = sc > 0.f ? sc : 0.2f * sc;
            p = __expf(sc);
        }
        psum += p;
        const int cnt = min(32, re - j0);
        for (int k = 0; k < cnt; k++) {
            const float pk = __shfl_sync(0xFFFFFFFFu, p, k);
            const int sk = __shfl_sync(0xFFFFFFFFu, s, k);
            const float4 v = reinterpret_cast<const float4*>(wx + (size_t)sk * 128)[lane];
            acc.x += v.x * pk;
            acc.y += v.y * pk;
            acc.z += v.z * pk;
            acc.w += v.w * pk;
        }
    }
#pragma unroll
    for (int o = 16; o; o >>= 1) psum += __shfl_xor_sync(0xFFFFFFFFu, psum, o);
    const float inv = psum > 0.f ? 1.f / psum : 0.f;

    const float4 r = reinterpret_cast<const float4*>(res + (size_t)d * 128)[lane];
    float4 v;
    v.x = acc.x * inv + r.x;
    v.y = acc.y * inv + r.y;
    v.z = acc.z * inv + r.z;
    v.w = acc.w * inv + r.w;
    v.x = v.x > 0.f ? v.x : expm1f(v.x);
    v.y = v.y > 0.f ? v.y : expm1f(v.y);
    v.z = v.z > 0.f ? v.z : expm1f(v.z);
    v.w = v.w > 0.f ? v.w : expm1f(v.w);
    if (fin) {
        float ss = v.x * v.x + v.y * v.y + v.z * v.z + v.w * v.w;
#pragma unroll
        for (int o = 16; o; o >>= 1) ss += __shfl_xor_sync(0xFFFFFFFFu, ss, o);
        const float nrm = 1.f / fmaxf(sqrtf(ss), 1e-12f);
        v.x *= nrm; v.y *= nrm; v.z *= nrm; v.w *= nrm;
    }
    reinterpret_cast<float4*>(hout + (size_t)d * 128)[lane] = v;
}

// ---------------- launch ----------------
extern "C" void kernel_launch(void* const* d_in, const int* in_sizes, int n_in,
                              void* d_out, int out_size) {
    const float* x = (const float*)d_in[0];
    const int* ei = (const int*)d_in[1];
    const int* et = (const int*)d_in[2];
    const float* l1W = (const float*)d_in[3];
    const float* l1b = (const float*)d_in[4];
    const float* l2W = (const float*)d_in[5];
    const float* l2b = (const float*)d_in[6];
    const float* W1 = (const float*)d_in[7];
    const float* Wr1 = (const float*)d_in[8];
    const float* a1 = (const float*)d_in[9];
    const float* Wres1 = (const float*)d_in[10];
    const float* rel1 = (const float*)d_in[11];
    const float* W2 = (const float*)d_in[12];
    const float* Wr2 = (const float*)d_in[13];
    const float* a2 = (const float*)d_in[14];
    const float* Wres2 = (const float*)d_in[15];
    const float* rel2 = (const float*)d_in[16];

    const int N = in_sizes[0] / IN_CH;
    const int E = in_sizes[2];
    const int* src = ei;
    const int* dst = ei + E;

    float *h, *wx, *agg, *sA, *sB, *relC;
    int *cnt, *off, *cur, *csr_src, *csr_et;
    cudaGetSymbolAddress((void**)&h, g_h);
    cudaGetSymbolAddress((void**)&wx, g_wx);
    cudaGetSymbolAddress((void**)&agg, g_agg);
    cudaGetSymbolAddress((void**)&sA, g_sA);
    cudaGetSymbolAddress((void**)&sB, g_sB);
    cudaGetSymbolAddress((void**)&relC, g_relC);
    cudaGetSymbolAddress((void**)&cnt, g_cnt);
    cudaGetSymbolAddress((void**)&off, g_off);
    cudaGetSymbolAddress((void**)&cur, g_cur);
    cudaGetSymbolAddress((void**)&csr_src, g_csr_src);
    cudaGetSymbolAddress((void**)&csr_et, g_csr_et);

    const dim3 gGemm1(cdiv(N, 128), 1);
    const dim3 gGemm2(cdiv(N, 128), 2);
    const int gNodeWarp = cdiv(N, 8);
    const int gEdge = cdiv(E, 256);

    // CSR build (once per launch; graph shared by both layers)
    cudaMemsetAsync(cnt, 0, N * sizeof(int));
    count_kernel<<<gEdge, 256>>>(dst, cnt, E);
    scan_kernel<<<1, 1024>>>(cnt, off, cur, N, E);
    fill_kernel<<<gEdge, 256>>>(src, dst, et, cur, csr_src, csr_et, E);

    // layer 0: h = leaky_relu(x @ l1W^T + b, 0.01)
    gemm_mma<<<gGemm1, 256>>>(x, l1W, l1b, h, nullptr, nullptr, nullptr, nullptr, nullptr,
                              N, IN_CH, F_BIASLEAKY);

    const float* Ws[2] = {W1, W2};
    const float* Wrs[2] = {Wr1, Wr2};
    const float* as[2] = {a1, a2};
    const float* Wress[2] = {Wres1, Wres2};
    const float* rels[2] = {rel1, rel2};

    for (int l = 0; l < 2; l++) {
        relc_kernel<<<1, 1024>>>(Wrs[l], as[l], rels[l], relC);
        // y=0: wx = h@W^T (+rowdot -> sA,sB); y=1: agg = h@Wres^T (residual)
        gemm_mma<<<gGemm2, 256>>>(h, Ws[l], nullptr, wx, Wress[l], agg, as[l], sA, sB,
                                  N, HID, F_ROWDOT);
        dst_fused_kernel<<<gNodeWarp, 256>>>(wx, agg, sA, sB, relC, off, csr_src, csr_et,
                                             h, N, l == 1 ? 1 : 0);
    }

    // final: out = leaky_relu(h @ l2W^T + l2b, 0.01)
    gemm_mma<<<gGemm1, 256>>>(h, l2W, l2b, (float*)d_out, nullptr, nullptr, nullptr, nullptr,
                              nullptr, N, HID, F_BIASLEAKY);
}

// round 13
// speedup vs baseline: 1.5747x; 1.0799x over previous
#include <cuda_runtime.h>
#include <cuda_fp16.h>
#include <math.h>

// ---------------- problem constants ----------------
#define MAX_NODES 50000
#define MAX_EDGES 600000
#define IN_CH 768
#define HID 128
#define REL_DIM 200
#define NUM_RELS 5

// ---------------- scratch (device globals) ----------------
__device__ float g_h[MAX_NODES * HID];
__device__ float g_wx[MAX_NODES * HID];
__device__ float g_agg[MAX_NODES * HID];
__device__ float g_sA[MAX_NODES];
__device__ float g_sB[MAX_NODES];
__device__ float g_relC[8];
__device__ int g_cnt[MAX_NODES];
__device__ int g_off[MAX_NODES + 1];
__device__ int g_cur[MAX_NODES];
__device__ int g_csr_src[MAX_EDGES];
__device__ int g_csr_et[MAX_EDGES];

static inline int cdiv(int a, int b) { return (a + b - 1) / b; }

__device__ __forceinline__ unsigned hpack(__half a, __half b) {
    unsigned short ua = *(unsigned short*)&a;
    unsigned short ub = *(unsigned short*)&b;
    return (unsigned)ua | ((unsigned)ub << 16);
}
__device__ __forceinline__ unsigned cvt2h(float x, float y) {
    return hpack(__float2half_rn(x), __float2half_rn(y));
}
__device__ __forceinline__ void split2h(float x, float y, unsigned& hi, unsigned& lo) {
    __half h0 = __float2half_rn(x), h1 = __float2half_rn(y);
    __half l0 = __float2half_rn(x - __half2float(h0));
    __half l1 = __float2half_rn(y - __half2float(h1));
    hi = hpack(h0, h1);
    lo = hpack(l0, l1);
}

// ---------------- HMMA fp16 GEMM (R7-proven structure; SPLIT templated) --------
// C[M,128] = A[M,K]fp32 @ B[128,K]fp32^T. A rounded fp16 in regs.
// SPLIT=1: B split hi/lo, C = A16*Bhi + A16*Blo (err ~2^-12).
// SPLIT=0: B rounded fp16, C = A16*B16 (err ~2^-11; used for layer-0 only).
// CTA 128x128, BK=32, 8 warps (2x4). blockIdx.y selects (B0,C0,flags) or (B1,C1,0).
#define F_BIASLEAKY 1
#define F_ROWDOT 2
#define GPAD 40

__device__ __forceinline__ void hmma16816(float* c, const unsigned* a, const unsigned* b) {
    asm volatile(
        "mma.sync.aligned.m16n8k16.row.col.f32.f16.f16.f32 "
        "{%0,%1,%2,%3}, {%4,%5,%6,%7}, {%8,%9}, {%0,%1,%2,%3};"
        : "+f"(c[0]), "+f"(c[1]), "+f"(c[2]), "+f"(c[3])
        : "r"(a[0]), "r"(a[1]), "r"(a[2]), "r"(a[3]), "r"(b[0]), "r"(b[1]));
}

template <bool SPLIT>
__global__ __launch_bounds__(256, 2) void gemm_mma(
    const float* __restrict__ A, const float* __restrict__ B0,
    const float* __restrict__ bias, float* __restrict__ C0,
    const float* __restrict__ B1, float* __restrict__ C1,
    const float* __restrict__ avec, float* __restrict__ sA, float* __restrict__ sB,
    int M, int K, int flags0) {
    __shared__ __align__(16) __half As16[128 * GPAD];
    __shared__ __align__(16) __half Bhi[128 * GPAD];
    __shared__ __align__(16) __half Blo[SPLIT ? 128 * GPAD : 8];
    __shared__ float s_red[2][128];

    const float* B = (blockIdx.y == 0) ? B0 : B1;
    float* C = (blockIdx.y == 0) ? C0 : C1;
    const int flags = (blockIdx.y == 0) ? flags0 : 0;

    const int tid = threadIdx.x;
    const int wid = tid >> 5;
    const int lane = tid & 31;
    const int wm = wid & 1;
    const int wn = wid >> 1;
    const int m0 = blockIdx.x * 128;
    const int g = lane >> 2;
    const int tq = lane & 3;

    float acc[4][4][4];
#pragma unroll
    for (int i = 0; i < 4; i++)
#pragma unroll
        for (int j = 0; j < 4; j++)
#pragma unroll
            for (int k = 0; k < 4; k++) acc[i][j][k] = 0.f;

    const int lrow = tid >> 1;
    const int lc0 = (tid & 1) << 4;
    const int gr = m0 + lrow;
    const float* aprow = A + (size_t)gr * K + lc0;
    const float* bprow = B + (size_t)lrow * K + lc0;

    float4 av[4], bv[4];
    // prologue: stage k-tile 0
#pragma unroll
    for (int q = 0; q < 4; q++) {
        av[q] = (gr < M) ? reinterpret_cast<const float4*>(aprow)[q]
                         : make_float4(0.f, 0.f, 0.f, 0.f);
        bv[q] = reinterpret_cast<const float4*>(bprow)[q];
    }

    const int nk = K >> 5;
    for (int it = 0; it < nk; it++) {
        __syncthreads();  // all warps done with smem from prev iter
        {
            unsigned ah[8];
#pragma unroll
            for (int q = 0; q < 4; q++) {
                ah[q * 2] = cvt2h(av[q].x, av[q].y);
                ah[q * 2 + 1] = cvt2h(av[q].z, av[q].w);
            }
            uint4* pa = reinterpret_cast<uint4*>(As16 + lrow * GPAD + lc0);
            pa[0] = make_uint4(ah[0], ah[1], ah[2], ah[3]);
            pa[1] = make_uint4(ah[4], ah[5], ah[6], ah[7]);
            if (SPLIT) {
                unsigned h[8], l[8];
#pragma unroll
                for (int q = 0; q < 4; q++) {
                    split2h(bv[q].x, bv[q].y, h[q * 2], l[q * 2]);
                    split2h(bv[q].z, bv[q].w, h[q * 2 + 1], l[q * 2 + 1]);
                }
                uint4* qh = reinterpret_cast<uint4*>(Bhi + lrow * GPAD + lc0);
                uint4* ql = reinterpret_cast<uint4*>(Blo + lrow * GPAD + lc0);
                qh[0] = make_uint4(h[0], h[1], h[2], h[3]);
                qh[1] = make_uint4(h[4], h[5], h[6], h[7]);
                ql[0] = make_uint4(l[0], l[1], l[2], l[3]);
                ql[1] = make_uint4(l[4], l[5], l[6], l[7]);
            } else {
                unsigned h[8];
#pragma unroll
                for (int q = 0; q < 4; q++) {
                    h[q * 2] = cvt2h(bv[q].x, bv[q].y);
                    h[q * 2 + 1] = cvt2h(bv[q].z, bv[q].w);
                }
                uint4* qh = reinterpret_cast<uint4*>(Bhi + lrow * GPAD + lc0);
                qh[0] = make_uint4(h[0], h[1], h[2], h[3]);
                qh[1] = make_uint4(h[4], h[5], h[6], h[7]);
            }
        }
        __syncthreads();
        // stage next k-tile (overlaps with MMA below)
        if (it + 1 < nk) {
            const float* ap = aprow + (it + 1) * 32;
            const float* bp = bprow + (it + 1) * 32;
#pragma unroll
            for (int q = 0; q < 4; q++) {
                av[q] = (gr < M) ? reinterpret_cast<const float4*>(ap)[q]
                                 : make_float4(0.f, 0.f, 0.f, 0.f);
                bv[q] = reinterpret_cast<const float4*>(bp)[q];
            }
        }
#pragma unroll
        for (int ks = 0; ks < 2; ks++) {
            const int cc = ks * 16 + tq * 2;
            unsigned a[4][4], b0[4][2];
#pragma unroll
            for (int nt = 0; nt < 4; nt++) {
                const int nb = wn * 32 + nt * 8 + g;
                b0[nt][0] = *reinterpret_cast<const unsigned*>(Bhi + nb * GPAD + cc);
                b0[nt][1] = *reinterpret_cast<const unsigned*>(Bhi + nb * GPAD + cc + 8);
            }
#pragma unroll
            for (int mt = 0; mt < 4; mt++) {
                const int rb = wm * 64 + mt * 16 + g;
                a[mt][0] = *reinterpret_cast<const unsigned*>(As16 + rb * GPAD + cc);
                a[mt][1] = *reinterpret_cast<const unsigned*>(As16 + (rb + 8) * GPAD + cc);
                a[mt][2] = *reinterpret_cast<const unsigned*>(As16 + rb * GPAD + cc + 8);
                a[mt][3] = *reinterpret_cast<const unsigned*>(As16 + (rb + 8) * GPAD + cc + 8);
            }
#pragma unroll
            for (int mt = 0; mt < 4; mt++)
#pragma unroll
                for (int nt = 0; nt < 4; nt++) hmma16816(acc[mt][nt], a[mt], b0[nt]);
            if (SPLIT) {
                unsigned b1[4][2];
#pragma unroll
                for (int nt = 0; nt < 4; nt++) {
                    const int nb = wn * 32 + nt * 8 + g;
                    b1[nt][0] = *reinterpret_cast<const unsigned*>(Blo + nb * GPAD + cc);
                    b1[nt][1] = *reinterpret_cast<const unsigned*>(Blo + nb * GPAD + cc + 8);
                }
#pragma unroll
                for (int mt = 0; mt < 4; mt++)
#pragma unroll
                    for (int nt = 0; nt < 4; nt++) hmma16816(acc[mt][nt], a[mt], b1[nt]);
            }
        }
    }

    // ---------------- epilogue ----------------
    const bool dorow = (flags & F_ROWDOT) != 0;
    if (dorow) {
        if (tid < 128) { s_red[0][tid] = 0.f; s_red[1][tid] = 0.f; }
        __syncthreads();
    }
#pragma unroll
    for (int mt = 0; mt < 4; mt++) {
        float pa[2] = {0.f, 0.f}, pb[2] = {0.f, 0.f};
#pragma unroll
        for (int nt = 0; nt < 4; nt++) {
            const int c = wn * 32 + nt * 8 + tq * 2;
            float bi0 = 0.f, bi1 = 0.f;
            if (flags & F_BIASLEAKY) { bi0 = bias[c]; bi1 = bias[c + 1]; }
            float aA0 = 0.f, aA1 = 0.f, aB0 = 0.f, aB1 = 0.f;
            if (dorow) {
                aA0 = avec[c]; aA1 = avec[c + 1];
                aB0 = avec[128 + c]; aB1 = avec[128 + c + 1];
            }
#pragma unroll
            for (int half = 0; half < 2; half++) {
                const int r = m0 + wm * 64 + mt * 16 + g + half * 8;
                float v0 = acc[mt][nt][half * 2 + 0];
                float v1 = acc[mt][nt][half * 2 + 1];
                if (flags & F_BIASLEAKY) {
                    v0 += bi0; v1 += bi1;
                    v0 = v0 > 0.f ? v0 : 0.01f * v0;
                    v1 = v1 > 0.f ? v1 : 0.01f * v1;
                }
                if (dorow) {
                    pa[half] += v0 * aA0 + v1 * aA1;
                    pb[half] += v0 * aB0 + v1 * aB1;
                }
                if (r < M)
                    *reinterpret_cast<float2*>(C + (size_t)r * 128 + c) = make_float2(v0, v1);
            }
        }
        if (dorow) {
#pragma unroll
            for (int half = 0; half < 2; half++) {
                const int lr = wm * 64 + mt * 16 + g + half * 8;
                atomicAdd(&s_red[0][lr], pa[half]);
                atomicAdd(&s_red[1][lr], pb[half]);
            }
        }
    }
    if (dorow) {
        __syncthreads();
        if (tid < 128 && m0 + tid < M) {
            sA[m0 + tid] = s_red[0][tid];
            sB[m0 + tid] = s_red[1][tid];
        }
    }
}

// ---------------- relC[r] = (rel[r] @ Wr^T) . aC ----------------
__global__ __launch_bounds__(1024) void relc_kernel(const float* __restrict__ Wr,
                                                    const float* __restrict__ a,
                                                    const float* __restrict__ rel,
                                                    float* __restrict__ relC) {
    __shared__ float part[4 * REL_DIM];
    __shared__ float v[REL_DIM];
    const int tid = threadIdx.x;
    const int t = tid & 255;
    const int p = tid >> 8;
    if (t < REL_DIM) {
        float s = 0.f;
        const int h0 = p * 32;
#pragma unroll 8
        for (int h = 0; h < 32; h++) s += a[2 * HID + h0 + h] * Wr[(size_t)(h0 + h) * REL_DIM + t];
        part[p * REL_DIM + t] = s;
    }
    __syncthreads();
    if (tid < REL_DIM)
        v[tid] = part[tid] + part[REL_DIM + tid] + part[2 * REL_DIM + tid] + part[3 * REL_DIM + tid];
    __syncthreads();
    const int r = tid >> 5;
    const int lane = tid & 31;
    if (r < NUM_RELS) {
        float s = 0.f;
        for (int k = lane; k < REL_DIM; k += 32) s += rel[r * REL_DIM + k] * v[k];
#pragma unroll
        for (int o = 16; o; o >>= 1) s += __shfl_xor_sync(0xFFFFFFFFu, s, o);
        if (lane == 0) relC[r] = s;
    }
}

// ---------------- CSR build (by dst) ----------------
__global__ void count_kernel(const int* __restrict__ dst, int* __restrict__ cnt, int E) {
    const int e = blockIdx.x * blockDim.x + threadIdx.x;
    if (e < E) atomicAdd(cnt + dst[e], 1);
}

__global__ __launch_bounds__(1024) void scan_kernel(const int* __restrict__ cnt,
                                                    int* __restrict__ off,
                                                    int* __restrict__ cur, int N, int E) {
    __shared__ int part[1024];
    const int tid = threadIdx.x;
    const int chunk = (N + 1023) >> 10;
    const int s0 = tid * chunk;
    int s = 0;
    for (int i = 0; i < chunk; i++) {
        const int idx = s0 + i;
        if (idx < N) s += cnt[idx];
    }
    part[tid] = s;
    __syncthreads();
    for (int o = 1; o < 1024; o <<= 1) {
        int t = (tid >= o) ? part[tid - o] : 0;
        __syncthreads();
        part[tid] += t;
        __syncthreads();
    }
    int run = part[tid] - s;  // exclusive base
    for (int i = 0; i < chunk; i++) {
        const int idx = s0 + i;
        if (idx < N) {
            off[idx] = run;
            cur[idx] = run;
            run += cnt[idx];
        }
    }
    if (tid == 0) off[N] = E;
}

__global__ void fill_kernel(const int* __restrict__ src, const int* __restrict__ dst,
                            const int* __restrict__ et, int* __restrict__ cur,
                            int* __restrict__ csr_src, int* __restrict__ csr_et, int E) {
    const int e = blockIdx.x * blockDim.x + threadIdx.x;
    if (e >= E) return;
    const int pos = atomicAdd(cur + dst[e], 1);
    csr_src[pos] = src[e];
    csr_et[pos] = et[e];
}

// ---------------- fused per-dst attention: softmax + aggregate + residual + elu(+norm)
__global__ void dst_fused_kernel(const float* __restrict__ wx, const float* __restrict__ res,
                                 const float* __restrict__ sA, const float* __restrict__ sB,
                                 const float* __restrict__ relC, const int* __restrict__ off,
                                 const int* __restrict__ csr_src, const int* __restrict__ csr_et,
                                 float* __restrict__ hout, int N, int fin) {
    const int d = (blockIdx.x * blockDim.x + threadIdx.x) >> 5;
    if (d >= N) return;
    const int lane = threadIdx.x & 31;
    const int rs = off[d];
    const int re = off[d + 1];
    const float sAd = sA[d];

    float4 acc = make_float4(0.f, 0.f, 0.f, 0.f);
    float psum = 0.f;
    for (int j0 = rs; j0 < re; j0 += 32) {
        const int j = j0 + lane;
        float p = 0.f;
        int s = 0;
        if (j < re) {
            s = csr_src[j];
            const int t = csr_et[j];
            float sc = sAd + sB[s] + relC[t];
            sc = sc > 0.f ? sc : 0.2f * sc;
            p = __expf(sc);
        }
        psum += p;
        const int cnt = min(32, re - j0);
        for (int k = 0; k < cnt; k++) {
            const float pk = __shfl_sync(0xFFFFFFFFu, p, k);
            const int sk = __shfl_sync(0xFFFFFFFFu, s, k);
            const float4 v = reinterpret_cast<const float4*>(wx + (size_t)sk * 128)[lane];
            acc.x += v.x * pk;
            acc.y += v.y * pk;
            acc.z += v.z * pk;
            acc.w += v.w * pk;
        }
    }
#pragma unroll
    for (int o = 16; o; o >>= 1) psum += __shfl_xor_sync(0xFFFFFFFFu, psum, o);
    const float inv = psum > 0.f ? 1.f / psum : 0.f;

    const float4 r = reinterpret_cast<const float4*>(res + (size_t)d * 128)[lane];
    float4 v;
    v.x = acc.x * inv + r.x;
    v.y = acc.y * inv + r.y;
    v.z = acc.z * inv + r.z;
    v.w = acc.w * inv + r.w;
    v.x = v.x > 0.f ? v.x : expm1f(v.x);
    v.y = v.y > 0.f ? v.y : expm1f(v.y);
    v.z = v.z > 0.f ? v.z : expm1f(v.z);
    v.w = v.w > 0.f ? v.w : expm1f(v.w);
    if (fin) {
        float ss = v.x * v.x + v.y * v.y + v.z * v.z + v.w * v.w;
#pragma unroll
        for (int o = 16; o; o >>= 1) ss += __shfl_xor_sync(0xFFFFFFFFu, ss, o);
        const float nrm = 1.f / fmaxf(sqrtf(ss), 1e-12f);
        v.x *= nrm; v.y *= nrm; v.z *= nrm; v.w *= nrm;
    }
    reinterpret_cast<float4*>(hout + (size_t)d * 128)[lane] = v;
}

// ---------------- launch ----------------
extern "C" void kernel_launch(void* const* d_in, const int* in_sizes, int n_in,
                              void* d_out, int out_size) {
    const float* x = (const float*)d_in[0];
    const int* ei = (const int*)d_in[1];
    const int* et = (const int*)d_in[2];
    const float* l1W = (const float*)d_in[3];
    const float* l1b = (const float*)d_in[4];
    const float* l2W = (const float*)d_in[5];
    const float* l2b = (const float*)d_in[6];
    const float* W1 = (const float*)d_in[7];
    const float* Wr1 = (const float*)d_in[8];
    const float* a1 = (const float*)d_in[9];
    const float* Wres1 = (const float*)d_in[10];
    const float* rel1 = (const float*)d_in[11];
    const float* W2 = (const float*)d_in[12];
    const float* Wr2 = (const float*)d_in[13];
    const float* a2 = (const float*)d_in[14];
    const float* Wres2 = (const float*)d_in[15];
    const float* rel2 = (const float*)d_in[16];

    const int N = in_sizes[0] / IN_CH;
    const int E = in_sizes[2];
    const int* src = ei;
    const int* dst = ei + E;

    float *h, *wx, *agg, *sA, *sB, *relC;
    int *cnt, *off, *cur, *csr_src, *csr_et;
    cudaGetSymbolAddress((void**)&h, g_h);
    cudaGetSymbolAddress((void**)&wx, g_wx);
    cudaGetSymbolAddress((void**)&agg, g_agg);
    cudaGetSymbolAddress((void**)&sA, g_sA);
    cudaGetSymbolAddress((void**)&sB, g_sB);
    cudaGetSymbolAddress((void**)&relC, g_relC);
    cudaGetSymbolAddress((void**)&cnt, g_cnt);
    cudaGetSymbolAddress((void**)&off, g_off);
    cudaGetSymbolAddress((void**)&cur, g_cur);
    cudaGetSymbolAddress((void**)&csr_src, g_csr_src);
    cudaGetSymbolAddress((void**)&csr_et, g_csr_et);

    const dim3 gGemm1(cdiv(N, 128), 1);
    const dim3 gGemm2(cdiv(N, 128), 2);
    const int gNodeWarp = cdiv(N, 8);
    const int gEdge = cdiv(E, 256);

    // CSR build (once per launch; graph shared by both layers)
    cudaMemsetAsync(cnt, 0, N * sizeof(int));
    count_kernel<<<gEdge, 256>>>(dst, cnt, E);
    scan_kernel<<<1, 1024>>>(cnt, off, cur, N, E);
    fill_kernel<<<gEdge, 256>>>(src, dst, et, cur, csr_src, csr_et, E);

    // layer 0: h = leaky_relu(x @ l1W^T + b, 0.01)  [single-term fp16 path]
    gemm_mma<false><<<gGemm1, 256>>>(x, l1W, l1b, h, nullptr, nullptr, nullptr, nullptr,
                                     nullptr, N, IN_CH, F_BIASLEAKY);

    const float* Ws[2] = {W1, W2};
    const float* Wrs[2] = {Wr1, Wr2};
    const float* as[2] = {a1, a2};
    const float* Wress[2] = {Wres1, Wres2};
    const float* rels[2] = {rel1, rel2};

    for (int l = 0; l < 2; l++) {
        relc_kernel<<<1, 1024>>>(Wrs[l], as[l], rels[l], relC);
        // y=0: wx = h@W^T (+rowdot -> sA,sB); y=1: agg = h@Wres^T (residual)
        gemm_mma<true><<<gGemm2, 256>>>(h, Ws[l], nullptr, wx, Wress[l], agg, as[l], sA, sB,
                                        N, HID, F_ROWDOT);
        dst_fused_kernel<<<gNodeWarp, 256>>>(wx, agg, sA, sB, relC, off, csr_src, csr_et,
                                             h, N, l == 1 ? 1 : 0);
    }

    // final: out = leaky_relu(h @ l2W^T + l2b, 0.01)
    gemm_mma<true><<<gGemm1, 256>>>(h, l2W, l2b, (float*)d_out, nullptr, nullptr, nullptr,
                                    nullptr, nullptr, N, HID, F_BIASLEAKY);
}

// round 14
// speedup vs baseline: 1.7015x; 1.0805x over previous
#include <cuda_runtime.h>
#include <cuda_fp16.h>
#include <math.h>

// ---------------- problem constants ----------------
#define MAX_NODES 50000
#define MAX_EDGES 600000
#define IN_CH 768
#define HID 128
#define REL_DIM 200
#define NUM_RELS 5

// ---------------- scratch (device globals) ----------------
__device__ float g_h[MAX_NODES * HID];
__device__ float g_wx[MAX_NODES * HID];
__device__ float g_agg[MAX_NODES * HID];
__device__ float g_sA[MAX_NODES];
__device__ float g_sB[MAX_NODES];
__device__ float g_relC[8];
__device__ int g_cnt[MAX_NODES];
__device__ int g_off[MAX_NODES + 1];
__device__ int g_cur[MAX_NODES];
__device__ int g_csr_src[MAX_EDGES];
__device__ int g_csr_et[MAX_EDGES];

static inline int cdiv(int a, int b) { return (a + b - 1) / b; }

__device__ __forceinline__ unsigned hpack(__half a, __half b) {
    unsigned short ua = *(unsigned short*)&a;
    unsigned short ub = *(unsigned short*)&b;
    return (unsigned)ua | ((unsigned)ub << 16);
}
__device__ __forceinline__ unsigned cvt2h(float x, float y) {
    return hpack(__float2half_rn(x), __float2half_rn(y));
}
__device__ __forceinline__ void split2h(float x, float y, unsigned& hi, unsigned& lo) {
    __half h0 = __float2half_rn(x), h1 = __float2half_rn(y);
    __half l0 = __float2half_rn(x - __half2float(h0));
    __half l1 = __float2half_rn(y - __half2float(h1));
    hi = hpack(h0, h1);
    lo = hpack(l0, l1);
}

// ---------------- HMMA fp16 GEMM (R7-proven structure; SPLIT templated) --------
// C[M,128] = A[M,K]fp32 @ B[128,K]fp32^T. A rounded fp16 in regs.
// SPLIT=1: B split hi/lo, C = A16*Bhi + A16*Blo (err ~2^-12).
// SPLIT=0: B rounded fp16, C = A16*B16 (err ~sqrt2*2^-12).
// CTA 128x128, BK=32, 8 warps (2x4). blockIdx.y selects (B0,C0,flags) or (B1,C1,0).
#define F_BIASLEAKY 1
#define F_ROWDOT 2
#define GPAD 40

__device__ __forceinline__ void hmma16816(float* c, const unsigned* a, const unsigned* b) {
    asm volatile(
        "mma.sync.aligned.m16n8k16.row.col.f32.f16.f16.f32 "
        "{%0,%1,%2,%3}, {%4,%5,%6,%7}, {%8,%9}, {%0,%1,%2,%3};"
        : "+f"(c[0]), "+f"(c[1]), "+f"(c[2]), "+f"(c[3])
        : "r"(a[0]), "r"(a[1]), "r"(a[2]), "r"(a[3]), "r"(b[0]), "r"(b[1]));
}

template <bool SPLIT>
__global__ __launch_bounds__(256, 2) void gemm_mma(
    const float* __restrict__ A, const float* __restrict__ B0,
    const float* __restrict__ bias, float* __restrict__ C0,
    const float* __restrict__ B1, float* __restrict__ C1,
    const float* __restrict__ avec, float* __restrict__ sA, float* __restrict__ sB,
    int M, int K, int flags0) {
    __shared__ __align__(16) __half As16[128 * GPAD];
    __shared__ __align__(16) __half Bhi[128 * GPAD];
    __shared__ __align__(16) __half Blo[SPLIT ? 128 * GPAD : 8];
    __shared__ float s_red[2][128];

    const float* B = (blockIdx.y == 0) ? B0 : B1;
    float* C = (blockIdx.y == 0) ? C0 : C1;
    const int flags = (blockIdx.y == 0) ? flags0 : 0;

    const int tid = threadIdx.x;
    const int wid = tid >> 5;
    const int lane = tid & 31;
    const int wm = wid & 1;
    const int wn = wid >> 1;
    const int m0 = blockIdx.x * 128;
    const int g = lane >> 2;
    const int tq = lane & 3;

    float acc[4][4][4];
#pragma unroll
    for (int i = 0; i < 4; i++)
#pragma unroll
        for (int j = 0; j < 4; j++)
#pragma unroll
            for (int k = 0; k < 4; k++) acc[i][j][k] = 0.f;

    const int lrow = tid >> 1;
    const int lc0 = (tid & 1) << 4;
    const int gr = m0 + lrow;
    const float* aprow = A + (size_t)gr * K + lc0;
    const float* bprow = B + (size_t)lrow * K + lc0;

    float4 av[4], bv[4];
    // prologue: stage k-tile 0
#pragma unroll
    for (int q = 0; q < 4; q++) {
        av[q] = (gr < M) ? reinterpret_cast<const float4*>(aprow)[q]
                         : make_float4(0.f, 0.f, 0.f, 0.f);
        bv[q] = reinterpret_cast<const float4*>(bprow)[q];
    }

    const int nk = K >> 5;
    for (int it = 0; it < nk; it++) {
        __syncthreads();  // all warps done with smem from prev iter
        {
            unsigned ah[8];
#pragma unroll
            for (int q = 0; q < 4; q++) {
                ah[q * 2] = cvt2h(av[q].x, av[q].y);
                ah[q * 2 + 1] = cvt2h(av[q].z, av[q].w);
            }
            uint4* pa = reinterpret_cast<uint4*>(As16 + lrow * GPAD + lc0);
            pa[0] = make_uint4(ah[0], ah[1], ah[2], ah[3]);
            pa[1] = make_uint4(ah[4], ah[5], ah[6], ah[7]);
            if (SPLIT) {
                unsigned h[8], l[8];
#pragma unroll
                for (int q = 0; q < 4; q++) {
                    split2h(bv[q].x, bv[q].y, h[q * 2], l[q * 2]);
                    split2h(bv[q].z, bv[q].w, h[q * 2 + 1], l[q * 2 + 1]);
                }
                uint4* qh = reinterpret_cast<uint4*>(Bhi + lrow * GPAD + lc0);
                uint4* ql = reinterpret_cast<uint4*>(Blo + lrow * GPAD + lc0);
                qh[0] = make_uint4(h[0], h[1], h[2], h[3]);
                qh[1] = make_uint4(h[4], h[5], h[6], h[7]);
                ql[0] = make_uint4(l[0], l[1], l[2], l[3]);
                ql[1] = make_uint4(l[4], l[5], l[6], l[7]);
            } else {
                unsigned h[8];
#pragma unroll
                for (int q = 0; q < 4; q++) {
                    h[q * 2] = cvt2h(bv[q].x, bv[q].y);
                    h[q * 2 + 1] = cvt2h(bv[q].z, bv[q].w);
                }
                uint4* qh = reinterpret_cast<uint4*>(Bhi + lrow * GPAD + lc0);
                qh[0] = make_uint4(h[0], h[1], h[2], h[3]);
                qh[1] = make_uint4(h[4], h[5], h[6], h[7]);
            }
        }
        __syncthreads();
        // stage next k-tile (overlaps with MMA below)
        if (it + 1 < nk) {
            const float* ap = aprow + (it + 1) * 32;
            const float* bp = bprow + (it + 1) * 32;
#pragma unroll
            for (int q = 0; q < 4; q++) {
                av[q] = (gr < M) ? reinterpret_cast<const float4*>(ap)[q]
                                 : make_float4(0.f, 0.f, 0.f, 0.f);
                bv[q] = reinterpret_cast<const float4*>(bp)[q];
            }
        }
#pragma unroll
        for (int ks = 0; ks < 2; ks++) {
            const int cc = ks * 16 + tq * 2;
            unsigned a[4][4], b0[4][2];
#pragma unroll
            for (int nt = 0; nt < 4; nt++) {
                const int nb = wn * 32 + nt * 8 + g;
                b0[nt][0] = *reinterpret_cast<const unsigned*>(Bhi + nb * GPAD + cc);
                b0[nt][1] = *reinterpret_cast<const unsigned*>(Bhi + nb * GPAD + cc + 8);
            }
#pragma unroll
            for (int mt = 0; mt < 4; mt++) {
                const int rb = wm * 64 + mt * 16 + g;
                a[mt][0] = *reinterpret_cast<const unsigned*>(As16 + rb * GPAD + cc);
                a[mt][1] = *reinterpret_cast<const unsigned*>(As16 + (rb + 8) * GPAD + cc);
                a[mt][2] = *reinterpret_cast<const unsigned*>(As16 + rb * GPAD + cc + 8);
                a[mt][3] = *reinterpret_cast<const unsigned*>(As16 + (rb + 8) * GPAD + cc + 8);
            }
#pragma unroll
            for (int mt = 0; mt < 4; mt++)
#pragma unroll
                for (int nt = 0; nt < 4; nt++) hmma16816(acc[mt][nt], a[mt], b0[nt]);
            if (SPLIT) {
                unsigned b1[4][2];
#pragma unroll
                for (int nt = 0; nt < 4; nt++) {
                    const int nb = wn * 32 + nt * 8 + g;
                    b1[nt][0] = *reinterpret_cast<const unsigned*>(Blo + nb * GPAD + cc);
                    b1[nt][1] = *reinterpret_cast<const unsigned*>(Blo + nb * GPAD + cc + 8);
                }
#pragma unroll
                for (int mt = 0; mt < 4; mt++)
#pragma unroll
                    for (int nt = 0; nt < 4; nt++) hmma16816(acc[mt][nt], a[mt], b1[nt]);
            }
        }
    }

    // ---------------- epilogue ----------------
    const bool dorow = (flags & F_ROWDOT) != 0;
    if (dorow) {
        if (tid < 128) { s_red[0][tid] = 0.f; s_red[1][tid] = 0.f; }
        __syncthreads();
    }
#pragma unroll
    for (int mt = 0; mt < 4; mt++) {
        float pa[2] = {0.f, 0.f}, pb[2] = {0.f, 0.f};
#pragma unroll
        for (int nt = 0; nt < 4; nt++) {
            const int c = wn * 32 + nt * 8 + tq * 2;
            float bi0 = 0.f, bi1 = 0.f;
            if (flags & F_BIASLEAKY) { bi0 = bias[c]; bi1 = bias[c + 1]; }
            float aA0 = 0.f, aA1 = 0.f, aB0 = 0.f, aB1 = 0.f;
            if (dorow) {
                aA0 = avec[c]; aA1 = avec[c + 1];
                aB0 = avec[128 + c]; aB1 = avec[128 + c + 1];
            }
#pragma unroll
            for (int half = 0; half < 2; half++) {
                const int r = m0 + wm * 64 + mt * 16 + g + half * 8;
                float v0 = acc[mt][nt][half * 2 + 0];
                float v1 = acc[mt][nt][half * 2 + 1];
                if (flags & F_BIASLEAKY) {
                    v0 += bi0; v1 += bi1;
                    v0 = v0 > 0.f ? v0 : 0.01f * v0;
                    v1 = v1 > 0.f ? v1 : 0.01f * v1;
                }
                if (dorow) {
                    pa[half] += v0 * aA0 + v1 * aA1;
                    pb[half] += v0 * aB0 + v1 * aB1;
                }
                if (r < M)
                    *reinterpret_cast<float2*>(C + (size_t)r * 128 + c) = make_float2(v0, v1);
            }
        }
        if (dorow) {
#pragma unroll
            for (int half = 0; half < 2; half++) {
                const int lr = wm * 64 + mt * 16 + g + half * 8;
                atomicAdd(&s_red[0][lr], pa[half]);
                atomicAdd(&s_red[1][lr], pb[half]);
            }
        }
    }
    if (dorow) {
        __syncthreads();
        if (tid < 128 && m0 + tid < M) {
            sA[m0 + tid] = s_red[0][tid];
            sB[m0 + tid] = s_red[1][tid];
        }
    }
}

// ---------------- relC[r] = (rel[r] @ Wr^T) . aC ----------------
__global__ __launch_bounds__(1024) void relc_kernel(const float* __restrict__ Wr,
                                                    const float* __restrict__ a,
                                                    const float* __restrict__ rel,
                                                    float* __restrict__ relC) {
    __shared__ float part[4 * REL_DIM];
    __shared__ float v[REL_DIM];
    const int tid = threadIdx.x;
    const int t = tid & 255;
    const int p = tid >> 8;
    if (t < REL_DIM) {
        float s = 0.f;
        const int h0 = p * 32;
#pragma unroll 8
        for (int h = 0; h < 32; h++) s += a[2 * HID + h0 + h] * Wr[(size_t)(h0 + h) * REL_DIM + t];
        part[p * REL_DIM + t] = s;
    }
    __syncthreads();
    if (tid < REL_DIM)
        v[tid] = part[tid] + part[REL_DIM + tid] + part[2 * REL_DIM + tid] + part[3 * REL_DIM + tid];
    __syncthreads();
    const int r = tid >> 5;
    const int lane = tid & 31;
    if (r < NUM_RELS) {
        float s = 0.f;
        for (int k = lane; k < REL_DIM; k += 32) s += rel[r * REL_DIM + k] * v[k];
#pragma unroll
        for (int o = 16; o; o >>= 1) s += __shfl_xor_sync(0xFFFFFFFFu, s, o);
        if (lane == 0) relC[r] = s;
    }
}

// ---------------- CSR build (by dst) ----------------
__global__ void count_kernel(const int* __restrict__ dst, int* __restrict__ cnt, int E) {
    const int e = blockIdx.x * blockDim.x + threadIdx.x;
    if (e < E) atomicAdd(cnt + dst[e], 1);
}

__global__ __launch_bounds__(1024) void scan_kernel(const int* __restrict__ cnt,
                                                    int* __restrict__ off,
                                                    int* __restrict__ cur, int N, int E) {
    __shared__ int part[1024];
    const int tid = threadIdx.x;
    const int chunk = (N + 1023) >> 10;
    const int s0 = tid * chunk;
    int s = 0;
    for (int i = 0; i < chunk; i++) {
        const int idx = s0 + i;
        if (idx < N) s += cnt[idx];
    }
    part[tid] = s;
    __syncthreads();
    for (int o = 1; o < 1024; o <<= 1) {
        int t = (tid >= o) ? part[tid - o] : 0;
        __syncthreads();
        part[tid] += t;
        __syncthreads();
    }
    int run = part[tid] - s;  // exclusive base
    for (int i = 0; i < chunk; i++) {
        const int idx = s0 + i;
        if (idx < N) {
            off[idx] = run;
            cur[idx] = run;
            run += cnt[idx];
        }
    }
    if (tid == 0) off[N] = E;
}

__global__ void fill_kernel(const int* __restrict__ src, const int* __restrict__ dst,
                            const int* __restrict__ et, int* __restrict__ cur,
                            int* __restrict__ csr_src, int* __restrict__ csr_et, int E) {
    const int e = blockIdx.x * blockDim.x + threadIdx.x;
    if (e >= E) return;
    const int pos = atomicAdd(cur + dst[e], 1);
    csr_src[pos] = src[e];
    csr_et[pos] = et[e];
}

// ---------------- fused per-dst attention: softmax + aggregate + residual + elu(+norm)
__global__ void dst_fused_kernel(const float* __restrict__ wx, const float* __restrict__ res,
                                 const float* __restrict__ sA, const float* __restrict__ sB,
                                 const float* __restrict__ relC, const int* __restrict__ off,
                                 const int* __restrict__ csr_src, const int* __restrict__ csr_et,
                                 float* __restrict__ hout, int N, int fin) {
    const int d = (blockIdx.x * blockDim.x + threadIdx.x) >> 5;
    if (d >= N) return;
    const int lane = threadIdx.x & 31;
    const int rs = off[d];
    const int re = off[d + 1];
    const float sAd = sA[d];

    float4 acc = make_float4(0.f, 0.f, 0.f, 0.f);
    float psum = 0.f;
    for (int j0 = rs; j0 < re; j0 += 32) {
        const int j = j0 + lane;
        float p = 0.f;
        int s = 0;
        if (j < re) {
            s = csr_src[j];
            const int t = csr_et[j];
            float sc = sAd + sB[s] + relC[t];
            sc = sc > 0.f ? sc : 0.2f * sc;
            p = __expf(sc);
        }
        psum += p;
        const int cnt = min(32, re - j0);
        for (int k = 0; k < cnt; k++) {
            const float pk = __shfl_sync(0xFFFFFFFFu, p, k);
            const int sk = __shfl_sync(0xFFFFFFFFu, s, k);
            const float4 v = reinterpret_cast<const float4*>(wx + (size_t)sk * 128)[lane];
            acc.x += v.x * pk;
            acc.y += v.y * pk;
            acc.z += v.z * pk;
            acc.w += v.w * pk;
        }
    }
#pragma unroll
    for (int o = 16; o; o >>= 1) psum += __shfl_xor_sync(0xFFFFFFFFu, psum, o);
    const float inv = psum > 0.f ? 1.f / psum : 0.f;

    const float4 r = reinterpret_cast<const float4*>(res + (size_t)d * 128)[lane];
    float4 v;
    v.x = acc.x * inv + r.x;
    v.y = acc.y * inv + r.y;
    v.z = acc.z * inv + r.z;
    v.w = acc.w * inv + r.w;
    v.x = v.x > 0.f ? v.x : expm1f(v.x);
    v.y = v.y > 0.f ? v.y : expm1f(v.y);
    v.z = v.z > 0.f ? v.z : expm1f(v.z);
    v.w = v.w > 0.f ? v.w : expm1f(v.w);
    if (fin) {
        float ss = v.x * v.x + v.y * v.y + v.z * v.z + v.w * v.w;
#pragma unroll
        for (int o = 16; o; o >>= 1) ss += __shfl_xor_sync(0xFFFFFFFFu, ss, o);
        const float nrm = 1.f / fmaxf(sqrtf(ss), 1e-12f);
        v.x *= nrm; v.y *= nrm; v.z *= nrm; v.w *= nrm;
    }
    reinterpret_cast<float4*>(hout + (size_t)d * 128)[lane] = v;
}

// ---------------- launch ----------------
extern "C" void kernel_launch(void* const* d_in, const int* in_sizes, int n_in,
                              void* d_out, int out_size) {
    const float* x = (const float*)d_in[0];
    const int* ei = (const int*)d_in[1];
    const int* et = (const int*)d_in[2];
    const float* l1W = (const float*)d_in[3];
    const float* l1b = (const float*)d_in[4];
    const float* l2W = (const float*)d_in[5];
    const float* l2b = (const float*)d_in[6];
    const float* W1 = (const float*)d_in[7];
    const float* Wr1 = (const float*)d_in[8];
    const float* a1 = (const float*)d_in[9];
    const float* Wres1 = (const float*)d_in[10];
    const float* rel1 = (const float*)d_in[11];
    const float* W2 = (const float*)d_in[12];
    const float* Wr2 = (const float*)d_in[13];
    const float* a2 = (const float*)d_in[14];
    const float* Wres2 = (const float*)d_in[15];
    const float* rel2 = (const float*)d_in[16];

    const int N = in_sizes[0] / IN_CH;
    const int E = in_sizes[2];
    const int* src = ei;
    const int* dst = ei + E;

    float *h, *wx, *agg, *sA, *sB, *relC;
    int *cnt, *off, *cur, *csr_src, *csr_et;
    cudaGetSymbolAddress((void**)&h, g_h);
    cudaGetSymbolAddress((void**)&wx, g_wx);
    cudaGetSymbolAddress((void**)&agg, g_agg);
    cudaGetSymbolAddress((void**)&sA, g_sA);
    cudaGetSymbolAddress((void**)&sB, g_sB);
    cudaGetSymbolAddress((void**)&relC, g_relC);
    cudaGetSymbolAddress((void**)&cnt, g_cnt);
    cudaGetSymbolAddress((void**)&off, g_off);
    cudaGetSymbolAddress((void**)&cur, g_cur);
    cudaGetSymbolAddress((void**)&csr_src, g_csr_src);
    cudaGetSymbolAddress((void**)&csr_et, g_csr_et);

    const dim3 gGemm1(cdiv(N, 128), 1);
    const dim3 gGemm2(cdiv(N, 128), 2);
    const int gNodeWarp = cdiv(N, 8);
    const int gEdge = cdiv(E, 256);

    // CSR build (once per launch; graph shared by both layers)
    cudaMemsetAsync(cnt, 0, N * sizeof(int));
    count_kernel<<<gEdge, 256>>>(dst, cnt, E);
    scan_kernel<<<1, 1024>>>(cnt, off, cur, N, E);
    fill_kernel<<<gEdge, 256>>>(src, dst, et, cur, csr_src, csr_et, E);

    // layer 0: h = leaky_relu(x @ l1W^T + b, 0.01)  [single-term fp16]
    gemm_mma<false><<<gGemm1, 256>>>(x, l1W, l1b, h, nullptr, nullptr, nullptr, nullptr,
                                     nullptr, N, IN_CH, F_BIASLEAKY);

    const float* Ws[2] = {W1, W2};
    const float* Wrs[2] = {Wr1, Wr2};
    const float* as[2] = {a1, a2};
    const float* Wress[2] = {Wres1, Wres2};
    const float* rels[2] = {rel1, rel2};

    for (int l = 0; l < 2; l++) {
        relc_kernel<<<1, 1024>>>(Wrs[l], as[l], rels[l], relC);
        // y=0: wx = h@W^T (+rowdot -> sA,sB); y=1: agg = h@Wres^T  [single-term fp16]
        gemm_mma<false><<<gGemm2, 256>>>(h, Ws[l], nullptr, wx, Wress[l], agg, as[l], sA, sB,
                                         N, HID, F_ROWDOT);
        dst_fused_kernel<<<gNodeWarp, 256>>>(wx, agg, sA, sB, relC, off, csr_src, csr_et,
                                             h, N, l == 1 ? 1 : 0);
    }

    // final: out = leaky_relu(h @ l2W^T + l2b, 0.01)  [single-term fp16]
    gemm_mma<false><<<gGemm1, 256>>>(h, l2W, l2b, (float*)d_out, nullptr, nullptr, nullptr,
                                     nullptr, nullptr, N, HID, F_BIASLEAKY);
}

// round 15
// speedup vs baseline: 1.7108x; 1.0055x over previous
#include <cuda_runtime.h>
#include <cuda_fp16.h>
#include <math.h>

// ---------------- problem constants ----------------
#define MAX_NODES 50000
#define MAX_EDGES 600000
#define IN_CH 768
#define HID 128
#define REL_DIM 200
#define NUM_RELS 5

// ---------------- scratch (device globals) ----------------
__device__ float g_h[MAX_NODES * HID];
__device__ float g_wx[MAX_NODES * HID];
__device__ float g_agg[MAX_NODES * HID];
__device__ float g_sA[MAX_NODES];
__device__ float g_sB[MAX_NODES];
__device__ float g_relC[8];
__device__ int g_cnt[MAX_NODES];
__device__ int g_off[MAX_NODES + 1];
__device__ int g_cur[MAX_NODES];
__device__ int g_csr_src[MAX_EDGES];
__device__ int g_csr_et[MAX_EDGES];

static inline int cdiv(int a, int b) { return (a + b - 1) / b; }

__device__ __forceinline__ unsigned hpack(__half a, __half b) {
    unsigned short ua = *(unsigned short*)&a;
    unsigned short ub = *(unsigned short*)&b;
    return (unsigned)ua | ((unsigned)ub << 16);
}
__device__ __forceinline__ unsigned cvt2h(float x, float y) {
    return hpack(__float2half_rn(x), __float2half_rn(y));
}
__device__ __forceinline__ void split2h(float x, float y, unsigned& hi, unsigned& lo) {
    __half h0 = __float2half_rn(x), h1 = __float2half_rn(y);
    __half l0 = __float2half_rn(x - __half2float(h0));
    __half l1 = __float2half_rn(y - __half2float(h1));
    hi = hpack(h0, h1);
    lo = hpack(l0, l1);
}

// ---------------- HMMA fp16 GEMM (R7 structure + ldmatrix fragments) -----------
// C[M,128] = A[M,K]fp32 @ B[128,K]fp32^T. A rounded fp16 in regs.
// SPLIT=1: B split hi/lo, C = A16*Bhi + A16*Blo. SPLIT=0: C = A16*B16.
// CTA 128x128, BK=32, 8 warps (2x4). blockIdx.y selects (B0,C0,flags) or (B1,C1,0).
#define F_BIASLEAKY 1
#define F_ROWDOT 2
#define GPAD 40

__device__ __forceinline__ void hmma16816(float* c, const unsigned* a, const unsigned* b) {
    asm volatile(
        "mma.sync.aligned.m16n8k16.row.col.f32.f16.f16.f32 "
        "{%0,%1,%2,%3}, {%4,%5,%6,%7}, {%8,%9}, {%0,%1,%2,%3};"
        : "+f"(c[0]), "+f"(c[1]), "+f"(c[2]), "+f"(c[3])
        : "r"(a[0]), "r"(a[1]), "r"(a[2]), "r"(a[3]), "r"(b[0]), "r"(b[1]));
}
__device__ __forceinline__ void ldmatrix_x4(unsigned& r0, unsigned& r1, unsigned& r2,
                                            unsigned& r3, unsigned addr) {
    asm volatile("ldmatrix.sync.aligned.m8n8.x4.shared.b16 {%0,%1,%2,%3}, [%4];"
                 : "=r"(r0), "=r"(r1), "=r"(r2), "=r"(r3)
                 : "r"(addr));
}

template <bool SPLIT>
__global__ __launch_bounds__(256, 2) void gemm_mma(
    const float* __restrict__ A, const float* __restrict__ B0,
    const float* __restrict__ bias, float* __restrict__ C0,
    const float* __restrict__ B1, float* __restrict__ C1,
    const float* __restrict__ avec, float* __restrict__ sA, float* __restrict__ sB,
    int M, int K, int flags0) {
    __shared__ __align__(16) __half As16[128 * GPAD];
    __shared__ __align__(16) __half Bhi[128 * GPAD];
    __shared__ __align__(16) __half Blo[SPLIT ? 128 * GPAD : 8];
    __shared__ float s_red[2][128];

    const float* B = (blockIdx.y == 0) ? B0 : B1;
    float* C = (blockIdx.y == 0) ? C0 : C1;
    const int flags = (blockIdx.y == 0) ? flags0 : 0;

    const int tid = threadIdx.x;
    const int wid = tid >> 5;
    const int lane = tid & 31;
    const int wm = wid & 1;
    const int wn = wid >> 1;
    const int m0 = blockIdx.x * 128;
    const int g = lane >> 2;
    const int tq = lane & 3;

    float acc[4][4][4];
#pragma unroll
    for (int i = 0; i < 4; i++)
#pragma unroll
        for (int j = 0; j < 4; j++)
#pragma unroll
            for (int k = 0; k < 4; k++) acc[i][j][k] = 0.f;

    // ldmatrix lane base addresses (bytes), computed once (R8-verified mapping).
    unsigned addrA[4], addrBh[2], addrBl[2];
    {
        const int rowa = (lane & 7) + ((lane >> 3) & 1) * 8;
        const int cola = (lane >> 4) * 8;
#pragma unroll
        for (int mt = 0; mt < 4; mt++) {
            const int r = wm * 64 + mt * 16 + rowa;
            addrA[mt] = (unsigned)__cvta_generic_to_shared(As16) +
                        (unsigned)((r * GPAD + cola) * 2);
        }
        const int rowb = (lane & 7) + (lane >> 4) * 8;
        const int colb = ((lane >> 3) & 1) * 8;
#pragma unroll
        for (int p = 0; p < 2; p++) {
            const int r = wn * 32 + p * 16 + rowb;
            addrBh[p] = (unsigned)__cvta_generic_to_shared(Bhi) +
                        (unsigned)((r * GPAD + colb) * 2);
            addrBl[p] = (unsigned)__cvta_generic_to_shared(Blo) +
                        (unsigned)(SPLIT ? (r * GPAD + colb) * 2 : 0);
        }
    }

    const int lrow = tid >> 1;
    const int lc0 = (tid & 1) << 4;
    const int gr = m0 + lrow;
    const float* aprow = A + (size_t)gr * K + lc0;
    const float* bprow = B + (size_t)lrow * K + lc0;

    float4 av[4], bv[4];
    // prologue: stage k-tile 0
#pragma unroll
    for (int q = 0; q < 4; q++) {
        av[q] = (gr < M) ? reinterpret_cast<const float4*>(aprow)[q]
                         : make_float4(0.f, 0.f, 0.f, 0.f);
        bv[q] = reinterpret_cast<const float4*>(bprow)[q];
    }

    const int nk = K >> 5;
    for (int it = 0; it < nk; it++) {
        __syncthreads();  // all warps done with smem from prev iter
        {
            unsigned ah[8];
#pragma unroll
            for (int q = 0; q < 4; q++) {
                ah[q * 2] = cvt2h(av[q].x, av[q].y);
                ah[q * 2 + 1] = cvt2h(av[q].z, av[q].w);
            }
            uint4* pa = reinterpret_cast<uint4*>(As16 + lrow * GPAD + lc0);
            pa[0] = make_uint4(ah[0], ah[1], ah[2], ah[3]);
            pa[1] = make_uint4(ah[4], ah[5], ah[6], ah[7]);
            if (SPLIT) {
                unsigned h[8], l[8];
#pragma unroll
                for (int q = 0; q < 4; q++) {
                    split2h(bv[q].x, bv[q].y, h[q * 2], l[q * 2]);
                    split2h(bv[q].z, bv[q].w, h[q * 2 + 1], l[q * 2 + 1]);
                }
                uint4* qh = reinterpret_cast<uint4*>(Bhi + lrow * GPAD + lc0);
                uint4* ql = reinterpret_cast<uint4*>(Blo + lrow * GPAD + lc0);
                qh[0] = make_uint4(h[0], h[1], h[2], h[3]);
                qh[1] = make_uint4(h[4], h[5], h[6], h[7]);
                ql[0] = make_uint4(l[0], l[1], l[2], l[3]);
                ql[1] = make_uint4(l[4], l[5], l[6], l[7]);
            } else {
                unsigned h[8];
#pragma unroll
                for (int q = 0; q < 4; q++) {
                    h[q * 2] = cvt2h(bv[q].x, bv[q].y);
                    h[q * 2 + 1] = cvt2h(bv[q].z, bv[q].w);
                }
                uint4* qh = reinterpret_cast<uint4*>(Bhi + lrow * GPAD + lc0);
                qh[0] = make_uint4(h[0], h[1], h[2], h[3]);
                qh[1] = make_uint4(h[4], h[5], h[6], h[7]);
            }
        }
        __syncthreads();
        // stage next k-tile (overlaps with MMA below)
        if (it + 1 < nk) {
            const float* ap = aprow + (it + 1) * 32;
            const float* bp = bprow + (it + 1) * 32;
#pragma unroll
            for (int q = 0; q < 4; q++) {
                av[q] = (gr < M) ? reinterpret_cast<const float4*>(ap)[q]
                                 : make_float4(0.f, 0.f, 0.f, 0.f);
                bv[q] = reinterpret_cast<const float4*>(bp)[q];
            }
        }
#pragma unroll
        for (int ks = 0; ks < 2; ks++) {
            const unsigned koff = (unsigned)(ks * 32);  // 16 halves = 32 bytes
            unsigned a[4][4], b0[4][2];
#pragma unroll
            for (int mt = 0; mt < 4; mt++)
                ldmatrix_x4(a[mt][0], a[mt][1], a[mt][2], a[mt][3], addrA[mt] + koff);
#pragma unroll
            for (int p = 0; p < 2; p++)
                ldmatrix_x4(b0[p * 2][0], b0[p * 2][1], b0[p * 2 + 1][0], b0[p * 2 + 1][1],
                            addrBh[p] + koff);
#pragma unroll
            for (int mt = 0; mt < 4; mt++)
#pragma unroll
                for (int nt = 0; nt < 4; nt++) hmma16816(acc[mt][nt], a[mt], b0[nt]);
            if (SPLIT) {
                unsigned b1[4][2];
#pragma unroll
                for (int p = 0; p < 2; p++)
                    ldmatrix_x4(b1[p * 2][0], b1[p * 2][1], b1[p * 2 + 1][0],
                                b1[p * 2 + 1][1], addrBl[p] + koff);
#pragma unroll
                for (int mt = 0; mt < 4; mt++)
#pragma unroll
                    for (int nt = 0; nt < 4; nt++) hmma16816(acc[mt][nt], a[mt], b1[nt]);
            }
        }
    }

    // ---------------- epilogue ----------------
    const bool dorow = (flags & F_ROWDOT) != 0;
    if (dorow) {
        if (tid < 128) { s_red[0][tid] = 0.f; s_red[1][tid] = 0.f; }
        __syncthreads();
    }
#pragma unroll
    for (int mt = 0; mt < 4; mt++) {
        float pa[2] = {0.f, 0.f}, pb[2] = {0.f, 0.f};
#pragma unroll
        for (int nt = 0; nt < 4; nt++) {
            const int c = wn * 32 + nt * 8 + tq * 2;
            float bi0 = 0.f, bi1 = 0.f;
            if (flags & F_BIASLEAKY) { bi0 = bias[c]; bi1 = bias[c + 1]; }
            float aA0 = 0.f, aA1 = 0.f, aB0 = 0.f, aB1 = 0.f;
            if (dorow) {
                aA0 = avec[c]; aA1 = avec[c + 1];
                aB0 = avec[128 + c]; aB1 = avec[128 + c + 1];
            }
#pragma unroll
            for (int half = 0; half < 2; half++) {
                const int r = m0 + wm * 64 + mt * 16 + g + half * 8;
                float v0 = acc[mt][nt][half * 2 + 0];
                float v1 = acc[mt][nt][half * 2 + 1];
                if (flags & F_BIASLEAKY) {
                    v0 += bi0; v1 += bi1;
                    v0 = v0 > 0.f ? v0 : 0.01f * v0;
                    v1 = v1 > 0.f ? v1 : 0.01f * v1;
                }
                if (dorow) {
                    pa[half] += v0 * aA0 + v1 * aA1;
                    pb[half] += v0 * aB0 + v1 * aB1;
                }
                if (r < M)
                    *reinterpret_cast<float2*>(C + (size_t)r * 128 + c) = make_float2(v0, v1);
            }
        }
        if (dorow) {
#pragma unroll
            for (int half = 0; half < 2; half++) {
                const int lr = wm * 64 + mt * 16 + g + half * 8;
                atomicAdd(&s_red[0][lr], pa[half]);
                atomicAdd(&s_red[1][lr], pb[half]);
            }
        }
    }
    if (dorow) {
        __syncthreads();
        if (tid < 128 && m0 + tid < M) {
            sA[m0 + tid] = s_red[0][tid];
            sB[m0 + tid] = s_red[1][tid];
        }
    }
}

// ---------------- relC[r] = (rel[r] @ Wr^T) . aC ----------------
__global__ __launch_bounds__(1024) void relc_kernel(const float* __restrict__ Wr,
                                                    const float* __restrict__ a,
                                                    const float* __restrict__ rel,
                                                    float* __restrict__ relC) {
    __shared__ float part[4 * REL_DIM];
    __shared__ float v[REL_DIM];
    const int tid = threadIdx.x;
    const int t = tid & 255;
    const int p = tid >> 8;
    if (t < REL_DIM) {
        float s = 0.f;
        const int h0 = p * 32;
#pragma unroll 8
        for (int h = 0; h < 32; h++) s += a[2 * HID + h0 + h] * Wr[(size_t)(h0 + h) * REL_DIM + t];
        part[p * REL_DIM + t] = s;
    }
    __syncthreads();
    if (tid < REL_DIM)
        v[tid] = part[tid] + part[REL_DIM + tid] + part[2 * REL_DIM + tid] + part[3 * REL_DIM + tid];
    __syncthreads();
    const int r = tid >> 5;
    const int lane = tid & 31;
    if (r < NUM_RELS) {
        float s = 0.f;
        for (int k = lane; k < REL_DIM; k += 32) s += rel[r * REL_DIM + k] * v[k];
#pragma unroll
        for (int o = 16; o; o >>= 1) s += __shfl_xor_sync(0xFFFFFFFFu, s, o);
        if (lane == 0) relC[r] = s;
    }
}

// ---------------- CSR build (by dst) ----------------
__global__ void count_kernel(const int* __restrict__ dst, int* __restrict__ cnt, int E) {
    const int e = blockIdx.x * blockDim.x + threadIdx.x;
    if (e < E) atomicAdd(cnt + dst[e], 1);
}

__global__ __launch_bounds__(1024) void scan_kernel(const int* __restrict__ cnt,
                                                    int* __restrict__ off,
                                                    int* __restrict__ cur, int N, int E) {
    __shared__ int part[1024];
    const int tid = threadIdx.x;
    const int chunk = (N + 1023) >> 10;
    const int s0 = tid * chunk;
    int s = 0;
    for (int i = 0; i < chunk; i++) {
        const int idx = s0 + i;
        if (idx < N) s += cnt[idx];
    }
    part[tid] = s;
    __syncthreads();
    for (int o = 1; o < 1024; o <<= 1) {
        int t = (tid >= o) ? part[tid - o] : 0;
        __syncthreads();
        part[tid] += t;
        __syncthreads();
    }
    int run = part[tid] - s;  // exclusive base
    for (int i = 0; i < chunk; i++) {
        const int idx = s0 + i;
        if (idx < N) {
            off[idx] = run;
            cur[idx] = run;
            run += cnt[idx];
        }
    }
    if (tid == 0) off[N] = E;
}

__global__ void fill_kernel(const int* __restrict__ src, const int* __restrict__ dst,
                            const int* __restrict__ et, int* __restrict__ cur,
                            int* __restrict__ csr_src, int* __restrict__ csr_et, int E) {
    const int e = blockIdx.x * blockDim.x + threadIdx.x;
    if (e >= E) return;
    const int pos = atomicAdd(cur + dst[e], 1);
    csr_src[pos] = src[e];
    csr_et[pos] = et[e];
}

// ---------------- fused per-dst attention: softmax + aggregate + residual + elu(+norm)
__global__ void dst_fused_kernel(const float* __restrict__ wx, const float* __restrict__ res,
                                 const float* __restrict__ sA, const float* __restrict__ sB,
                                 const float* __restrict__ relC, const int* __restrict__ off,
                                 const int* __restrict__ csr_src, const int* __restrict__ csr_et,
                                 float* __restrict__ hout, int N, int fin) {
    const int d = (blockIdx.x * blockDim.x + threadIdx.x) >> 5;
    if (d >= N) return;
    const int lane = threadIdx.x & 31;
    const int rs = off[d];
    const int re = off[d + 1];
    const float sAd = sA[d];

    float4 acc = make_float4(0.f, 0.f, 0.f, 0.f);
    float psum = 0.f;
    for (int j0 = rs; j0 < re; j0 += 32) {
        const int j = j0 + lane;
        float p = 0.f;
        int s = 0;
        if (j < re) {
            s = csr_src[j];
            const int t = csr_et[j];
            float sc = sAd + sB[s] + relC[t];
            sc = sc > 0.f ? sc : 0.2f * sc;
            p = __expf(sc);
        }
        psum += p;
        const int cnt = min(32, re - j0);
        for (int k = 0; k < cnt; k++) {
            const float pk = __shfl_sync(0xFFFFFFFFu, p, k);
            const int sk = __shfl_sync(0xFFFFFFFFu, s, k);
            const float4 v = reinterpret_cast<const float4*>(wx + (size_t)sk * 128)[lane];
            acc.x += v.x * pk;
            acc.y += v.y * pk;
            acc.z += v.z * pk;
            acc.w += v.w * pk;
        }
    }
#pragma unroll
    for (int o = 16; o; o >>= 1) psum += __shfl_xor_sync(0xFFFFFFFFu, psum, o);
    const float inv = psum > 0.f ? 1.f / psum : 0.f;

    const float4 r = reinterpret_cast<const float4*>(res + (size_t)d * 128)[lane];
    float4 v;
    v.x = acc.x * inv + r.x;
    v.y = acc.y * inv + r.y;
    v.z = acc.z * inv + r.z;
    v.w = acc.w * inv + r.w;
    v.x = v.x > 0.f ? v.x : expm1f(v.x);
    v.y = v.y > 0.f ? v.y : expm1f(v.y);
    v.z = v.z > 0.f ? v.z : expm1f(v.z);
    v.w = v.w > 0.f ? v.w : expm1f(v.w);
    if (fin) {
        float ss = v.x * v.x + v.y * v.y + v.z * v.z + v.w * v.w;
#pragma unroll
        for (int o = 16; o; o >>= 1) ss += __shfl_xor_sync(0xFFFFFFFFu, ss, o);
        const float nrm = 1.f / fmaxf(sqrtf(ss), 1e-12f);
        v.x *= nrm; v.y *= nrm; v.z *= nrm; v.w *= nrm;
    }
    reinterpret_cast<float4*>(hout + (size_t)d * 128)[lane] = v;
}

// ---------------- launch ----------------
extern "C" void kernel_launch(void* const* d_in, const int* in_sizes, int n_in,
                              void* d_out, int out_size) {
    const float* x = (const float*)d_in[0];
    const int* ei = (const int*)d_in[1];
    const int* et = (const int*)d_in[2];
    const float* l1W = (const float*)d_in[3];
    const float* l1b = (const float*)d_in[4];
    const float* l2W = (const float*)d_in[5];
    const float* l2b = (const float*)d_in[6];
    const float* W1 = (const float*)d_in[7];
    const float* Wr1 = (const float*)d_in[8];
    const float* a1 = (const float*)d_in[9];
    const float* Wres1 = (const float*)d_in[10];
    const float* rel1 = (const float*)d_in[11];
    const float* W2 = (const float*)d_in[12];
    const float* Wr2 = (const float*)d_in[13];
    const float* a2 = (const float*)d_in[14];
    const float* Wres2 = (const float*)d_in[15];
    const float* rel2 = (const float*)d_in[16];

    const int N = in_sizes[0] / IN_CH;
    const int E = in_sizes[2];
    const int* src = ei;
    const int* dst = ei + E;

    float *h, *wx, *agg, *sA, *sB, *relC;
    int *cnt, *off, *cur, *csr_src, *csr_et;
    cudaGetSymbolAddress((void**)&h, g_h);
    cudaGetSymbolAddress((void**)&wx, g_wx);
    cudaGetSymbolAddress((void**)&agg, g_agg);
    cudaGetSymbolAddress((void**)&sA, g_sA);
    cudaGetSymbolAddress((void**)&sB, g_sB);
    cudaGetSymbolAddress((void**)&relC, g_relC);
    cudaGetSymbolAddress((void**)&cnt, g_cnt);
    cudaGetSymbolAddress((void**)&off, g_off);
    cudaGetSymbolAddress((void**)&cur, g_cur);
    cudaGetSymbolAddress((void**)&csr_src, g_csr_src);
    cudaGetSymbolAddress((void**)&csr_et, g_csr_et);

    const dim3 gGemm1(cdiv(N, 128), 1);
    const dim3 gGemm2(cdiv(N, 128), 2);
    const int gNodeWarp = cdiv(N, 8);
    const int gEdge = cdiv(E, 256);

    // CSR build (once per launch; graph shared by both layers)
    cudaMemsetAsync(cnt, 0, N * sizeof(int));
    count_kernel<<<gEdge, 256>>>(dst, cnt, E);
    scan_kernel<<<1, 1024>>>(cnt, off, cur, N, E);
    fill_kernel<<<gEdge, 256>>>(src, dst, et, cur, csr_src, csr_et, E);

    // layer 0: h = leaky_relu(x @ l1W^T + b, 0.01)  [single-term fp16]
    gemm_mma<false><<<gGemm1, 256>>>(x, l1W, l1b, h, nullptr, nullptr, nullptr, nullptr,
                                     nullptr, N, IN_CH, F_BIASLEAKY);

    const float* Ws[2] = {W1, W2};
    const float* Wrs[2] = {Wr1, Wr2};
    const float* as[2] = {a1, a2};
    const float* Wress[2] = {Wres1, Wres2};
    const float* rels[2] = {rel1, rel2};

    for (int l = 0; l < 2; l++) {
        relc_kernel<<<1, 1024>>>(Wrs[l], as[l], rels[l], relC);
        // y=0: wx = h@W^T (+rowdot -> sA,sB); y=1: agg = h@Wres^T  [single-term fp16]
        gemm_mma<false><<<gGemm2, 256>>>(h, Ws[l], nullptr, wx, Wress[l], agg, as[l], sA, sB,
                                         N, HID, F_ROWDOT);
        dst_fused_kernel<<<gNodeWarp, 256>>>(wx, agg, sA, sB, relC, off, csr_src, csr_et,
                                             h, N, l == 1 ? 1 : 0);
    }

    // final: out = leaky_relu(h @ l2W^T + l2b, 0.01)  [single-term fp16]
    gemm_mma<false><<<gGemm1, 256>>>(h, l2W, l2b, (float*)d_out, nullptr, nullptr, nullptr,
                                     nullptr, nullptr, N, HID, F_BIASLEAKY);
}

// round 16
// speedup vs baseline: 1.7385x; 1.0162x over previous
#include <cuda_runtime.h>
#include <cuda_fp16.h>
#include <math.h>

// ---------------- problem constants ----------------
#define MAX_NODES 50000
#define MAX_EDGES 600000
#define IN_CH 768
#define HID 128
#define REL_DIM 200
#define NUM_RELS 5

// ---------------- scratch (device globals) ----------------
__device__ float g_h[MAX_NODES * HID];
__device__ __half g_wx16[MAX_NODES * HID];
__device__ float g_agg[MAX_NODES * HID];
__device__ float g_sA[MAX_NODES];
__device__ float g_sB[MAX_NODES];
__device__ float g_relC[8];
__device__ int g_cnt[MAX_NODES];
__device__ int g_off[MAX_NODES + 1];
__device__ int g_cur[MAX_NODES];
__device__ int g_csr_src[MAX_EDGES];
__device__ int g_csr_et[MAX_EDGES];

static inline int cdiv(int a, int b) { return (a + b - 1) / b; }

__device__ __forceinline__ unsigned hpack(__half a, __half b) {
    unsigned short ua = *(unsigned short*)&a;
    unsigned short ub = *(unsigned short*)&b;
    return (unsigned)ua | ((unsigned)ub << 16);
}
__device__ __forceinline__ unsigned cvt2h(float x, float y) {
    return hpack(__float2half_rn(x), __float2half_rn(y));
}
__device__ __forceinline__ void split2h(float x, float y, unsigned& hi, unsigned& lo) {
    __half h0 = __float2half_rn(x), h1 = __float2half_rn(y);
    __half l0 = __float2half_rn(x - __half2float(h0));
    __half l1 = __float2half_rn(y - __half2float(h1));
    hi = hpack(h0, h1);
    lo = hpack(l0, l1);
}

// ---------------- HMMA fp16 GEMM (R7 structure + ldmatrix fragments) -----------
// C[M,128] = A[M,K]fp32 @ B[128,K]fp32^T. A rounded fp16 in regs.
// SPLIT=1: B split hi/lo. SPLIT=0: C = A16*B16 (current path for all GEMMs).
// F_C16: write C as fp16 (used for wx consumed by dst_fused).
// CTA 128x128, BK=32, 8 warps (2x4). blockIdx.y selects (B0,C0,flags) or (B1,C1,0).
#define F_BIASLEAKY 1
#define F_ROWDOT 2
#define F_C16 4
#define GPAD 40

__device__ __forceinline__ void hmma16816(float* c, const unsigned* a, const unsigned* b) {
    asm volatile(
        "mma.sync.aligned.m16n8k16.row.col.f32.f16.f16.f32 "
        "{%0,%1,%2,%3}, {%4,%5,%6,%7}, {%8,%9}, {%0,%1,%2,%3};"
        : "+f"(c[0]), "+f"(c[1]), "+f"(c[2]), "+f"(c[3])
        : "r"(a[0]), "r"(a[1]), "r"(a[2]), "r"(a[3]), "r"(b[0]), "r"(b[1]));
}
__device__ __forceinline__ void ldmatrix_x4(unsigned& r0, unsigned& r1, unsigned& r2,
                                            unsigned& r3, unsigned addr) {
    asm volatile("ldmatrix.sync.aligned.m8n8.x4.shared.b16 {%0,%1,%2,%3}, [%4];"
                 : "=r"(r0), "=r"(r1), "=r"(r2), "=r"(r3)
                 : "r"(addr));
}

template <bool SPLIT>
__global__ __launch_bounds__(256, 2) void gemm_mma(
    const float* __restrict__ A, const float* __restrict__ B0,
    const float* __restrict__ bias, float* __restrict__ C0, __half* __restrict__ Ch0,
    const float* __restrict__ B1, float* __restrict__ C1,
    const float* __restrict__ avec, float* __restrict__ sA, float* __restrict__ sB,
    int M, int K, int flags0) {
    __shared__ __align__(16) __half As16[128 * GPAD];
    __shared__ __align__(16) __half Bhi[128 * GPAD];
    __shared__ __align__(16) __half Blo[SPLIT ? 128 * GPAD : 8];
    __shared__ float s_red[2][128];

    const float* B = (blockIdx.y == 0) ? B0 : B1;
    float* C = (blockIdx.y == 0) ? C0 : C1;
    const int flags = (blockIdx.y == 0) ? flags0 : 0;

    const int tid = threadIdx.x;
    const int wid = tid >> 5;
    const int lane = tid & 31;
    const int wm = wid & 1;
    const int wn = wid >> 1;
    const int m0 = blockIdx.x * 128;
    const int g = lane >> 2;
    const int tq = lane & 3;

    float acc[4][4][4];
#pragma unroll
    for (int i = 0; i < 4; i++)
#pragma unroll
        for (int j = 0; j < 4; j++)
#pragma unroll
            for (int k = 0; k < 4; k++) acc[i][j][k] = 0.f;

    // ldmatrix lane base addresses (bytes), computed once (R8-verified mapping).
    unsigned addrA[4], addrBh[2], addrBl[2];
    {
        const int rowa = (lane & 7) + ((lane >> 3) & 1) * 8;
        const int cola = (lane >> 4) * 8;
#pragma unroll
        for (int mt = 0; mt < 4; mt++) {
            const int r = wm * 64 + mt * 16 + rowa;
            addrA[mt] = (unsigned)__cvta_generic_to_shared(As16) +
                        (unsigned)((r * GPAD + cola) * 2);
        }
        const int rowb = (lane & 7) + (lane >> 4) * 8;
        const int colb = ((lane >> 3) & 1) * 8;
#pragma unroll
        for (int p = 0; p < 2; p++) {
            const int r = wn * 32 + p * 16 + rowb;
            addrBh[p] = (unsigned)__cvta_generic_to_shared(Bhi) +
                        (unsigned)((r * GPAD + colb) * 2);
            addrBl[p] = (unsigned)__cvta_generic_to_shared(Blo) +
                        (unsigned)(SPLIT ? (r * GPAD + colb) * 2 : 0);
        }
    }

    const int lrow = tid >> 1;
    const int lc0 = (tid & 1) << 4;
    const int gr = m0 + lrow;
    const float* aprow = A + (size_t)gr * K + lc0;
    const float* bprow = B + (size_t)lrow * K + lc0;

    float4 av[4], bv[4];
    // prologue: stage k-tile 0
#pragma unroll
    for (int q = 0; q < 4; q++) {
        av[q] = (gr < M) ? reinterpret_cast<const float4*>(aprow)[q]
                         : make_float4(0.f, 0.f, 0.f, 0.f);
        bv[q] = reinterpret_cast<const float4*>(bprow)[q];
    }

    const int nk = K >> 5;
    for (int it = 0; it < nk; it++) {
        __syncthreads();  // all warps done with smem from prev iter
        {
            unsigned ah[8];
#pragma unroll
            for (int q = 0; q < 4; q++) {
                ah[q * 2] = cvt2h(av[q].x, av[q].y);
                ah[q * 2 + 1] = cvt2h(av[q].z, av[q].w);
            }
            uint4* pa = reinterpret_cast<uint4*>(As16 + lrow * GPAD + lc0);
            pa[0] = make_uint4(ah[0], ah[1], ah[2], ah[3]);
            pa[1] = make_uint4(ah[4], ah[5], ah[6], ah[7]);
            if (SPLIT) {
                unsigned h[8], l[8];
#pragma unroll
                for (int q = 0; q < 4; q++) {
                    split2h(bv[q].x, bv[q].y, h[q * 2], l[q * 2]);
                    split2h(bv[q].z, bv[q].w, h[q * 2 + 1], l[q * 2 + 1]);
                }
                uint4* qh = reinterpret_cast<uint4*>(Bhi + lrow * GPAD + lc0);
                uint4* ql = reinterpret_cast<uint4*>(Blo + lrow * GPAD + lc0);
                qh[0] = make_uint4(h[0], h[1], h[2], h[3]);
                qh[1] = make_uint4(h[4], h[5], h[6], h[7]);
                ql[0] = make_uint4(l[0], l[1], l[2], l[3]);
                ql[1] = make_uint4(l[4], l[5], l[6], l[7]);
            } else {
                unsigned h[8];
#pragma unroll
                for (int q = 0; q < 4; q++) {
                    h[q * 2] = cvt2h(bv[q].x, bv[q].y);
                    h[q * 2 + 1] = cvt2h(bv[q].z, bv[q].w);
                }
                uint4* qh = reinterpret_cast<uint4*>(Bhi + lrow * GPAD + lc0);
                qh[0] = make_uint4(h[0], h[1], h[2], h[3]);
                qh[1] = make_uint4(h[4], h[5], h[6], h[7]);
            }
        }
        __syncthreads();
        // stage next k-tile (overlaps with MMA below)
        if (it + 1 < nk) {
            const float* ap = aprow + (it + 1) * 32;
            const float* bp = bprow + (it + 1) * 32;
#pragma unroll
            for (int q = 0; q < 4; q++) {
                av[q] = (gr < M) ? reinterpret_cast<const float4*>(ap)[q]
                                 : make_float4(0.f, 0.f, 0.f, 0.f);
                bv[q] = reinterpret_cast<const float4*>(bp)[q];
            }
        }
#pragma unroll
        for (int ks = 0; ks < 2; ks++) {
            const unsigned koff = (unsigned)(ks * 32);  // 16 halves = 32 bytes
            unsigned a[4][4], b0[4][2];
#pragma unroll
            for (int mt = 0; mt < 4; mt++)
                ldmatrix_x4(a[mt][0], a[mt][1], a[mt][2], a[mt][3], addrA[mt] + koff);
#pragma unroll
            for (int p = 0; p < 2; p++)
                ldmatrix_x4(b0[p * 2][0], b0[p * 2][1], b0[p * 2 + 1][0], b0[p * 2 + 1][1],
                            addrBh[p] + koff);
#pragma unroll
            for (int mt = 0; mt < 4; mt++)
#pragma unroll
                for (int nt = 0; nt < 4; nt++) hmma16816(acc[mt][nt], a[mt], b0[nt]);
            if (SPLIT) {
                unsigned b1[4][2];
#pragma unroll
                for (int p = 0; p < 2; p++)
                    ldmatrix_x4(b1[p * 2][0], b1[p * 2][1], b1[p * 2 + 1][0],
                                b1[p * 2 + 1][1], addrBl[p] + koff);
#pragma unroll
                for (int mt = 0; mt < 4; mt++)
#pragma unroll
                    for (int nt = 0; nt < 4; nt++) hmma16816(acc[mt][nt], a[mt], b1[nt]);
            }
        }
    }

    // ---------------- epilogue ----------------
    const bool dorow = (flags & F_ROWDOT) != 0;
    if (dorow) {
        if (tid < 128) { s_red[0][tid] = 0.f; s_red[1][tid] = 0.f; }
        __syncthreads();
    }
#pragma unroll
    for (int mt = 0; mt < 4; mt++) {
        float pa[2] = {0.f, 0.f}, pb[2] = {0.f, 0.f};
#pragma unroll
        for (int nt = 0; nt < 4; nt++) {
            const int c = wn * 32 + nt * 8 + tq * 2;
            float bi0 = 0.f, bi1 = 0.f;
            if (flags & F_BIASLEAKY) { bi0 = bias[c]; bi1 = bias[c + 1]; }
            float aA0 = 0.f, aA1 = 0.f, aB0 = 0.f, aB1 = 0.f;
            if (dorow) {
                aA0 = avec[c]; aA1 = avec[c + 1];
                aB0 = avec[128 + c]; aB1 = avec[128 + c + 1];
            }
#pragma unroll
            for (int half = 0; half < 2; half++) {
                const int r = m0 + wm * 64 + mt * 16 + g + half * 8;
                float v0 = acc[mt][nt][half * 2 + 0];
                float v1 = acc[mt][nt][half * 2 + 1];
                if (flags & F_BIASLEAKY) {
                    v0 += bi0; v1 += bi1;
                    v0 = v0 > 0.f ? v0 : 0.01f * v0;
                    v1 = v1 > 0.f ? v1 : 0.01f * v1;
                }
                if (dorow) {
                    pa[half] += v0 * aA0 + v1 * aA1;
                    pb[half] += v0 * aB0 + v1 * aB1;
                }
                if (r < M) {
                    if (flags & F_C16)
                        *reinterpret_cast<unsigned*>(Ch0 + (size_t)r * 128 + c) = cvt2h(v0, v1);
                    else
                        *reinterpret_cast<float2*>(C + (size_t)r * 128 + c) = make_float2(v0, v1);
                }
            }
        }
        if (dorow) {
#pragma unroll
            for (int half = 0; half < 2; half++) {
                const int lr = wm * 64 + mt * 16 + g + half * 8;
                atomicAdd(&s_red[0][lr], pa[half]);
                atomicAdd(&s_red[1][lr], pb[half]);
            }
        }
    }
    if (dorow) {
        __syncthreads();
        if (tid < 128 && m0 + tid < M) {
            sA[m0 + tid] = s_red[0][tid];
            sB[m0 + tid] = s_red[1][tid];
        }
    }
}

// ---------------- relC[r] = (rel[r] @ Wr^T) . aC ----------------
__global__ __launch_bounds__(1024) void relc_kernel(const float* __restrict__ Wr,
                                                    const float* __restrict__ a,
                                                    const float* __restrict__ rel,
                                                    float* __restrict__ relC) {
    __shared__ float part[4 * REL_DIM];
    __shared__ float v[REL_DIM];
    const int tid = threadIdx.x;
    const int t = tid & 255;
    const int p = tid >> 8;
    if (t < REL_DIM) {
        float s = 0.f;
        const int h0 = p * 32;
#pragma unroll 8
        for (int h = 0; h < 32; h++) s += a[2 * HID + h0 + h] * Wr[(size_t)(h0 + h) * REL_DIM + t];
        part[p * REL_DIM + t] = s;
    }
    __syncthreads();
    if (tid < REL_DIM)
        v[tid] = part[tid] + part[REL_DIM + tid] + part[2 * REL_DIM + tid] + part[3 * REL_DIM + tid];
    __syncthreads();
    const int r = tid >> 5;
    const int lane = tid & 31;
    if (r < NUM_RELS) {
        float s = 0.f;
        for (int k = lane; k < REL_DIM; k += 32) s += rel[r * REL_DIM + k] * v[k];
#pragma unroll
        for (int o = 16; o; o >>= 1) s += __shfl_xor_sync(0xFFFFFFFFu, s, o);
        if (lane == 0) relC[r] = s;
    }
}

// ---------------- CSR build (by dst) ----------------
__global__ void count_kernel(const int* __restrict__ dst, int* __restrict__ cnt, int E) {
    const int e = blockIdx.x * blockDim.x + threadIdx.x;
    if (e < E) atomicAdd(cnt + dst[e], 1);
}

__global__ __launch_bounds__(1024) void scan_kernel(const int* __restrict__ cnt,
                                                    int* __restrict__ off,
                                                    int* __restrict__ cur, int N, int E) {
    __shared__ int part[1024];
    const int tid = threadIdx.x;
    const int chunk = (N + 1023) >> 10;
    const int s0 = tid * chunk;
    int s = 0;
    for (int i = 0; i < chunk; i++) {
        const int idx = s0 + i;
        if (idx < N) s += cnt[idx];
    }
    part[tid] = s;
    __syncthreads();
    for (int o = 1; o < 1024; o <<= 1) {
        int t = (tid >= o) ? part[tid - o] : 0;
        __syncthreads();
        part[tid] += t;
        __syncthreads();
    }
    int run = part[tid] - s;  // exclusive base
    for (int i = 0; i < chunk; i++) {
        const int idx = s0 + i;
        if (idx < N) {
            off[idx] = run;
            cur[idx] = run;
            run += cnt[idx];
        }
    }
    if (tid == 0) off[N] = E;
}

__global__ void fill_kernel(const int* __restrict__ src, const int* __restrict__ dst,
                            const int* __restrict__ et, int* __restrict__ cur,
                            int* __restrict__ csr_src, int* __restrict__ csr_et, int E) {
    const int e = blockIdx.x * blockDim.x + threadIdx.x;
    if (e >= E) return;
    const int pos = atomicAdd(cur + dst[e], 1);
    csr_src[pos] = src[e];
    csr_et[pos] = et[e];
}

// ---------------- fused per-dst attention (wx in fp16): softmax + agg + residual + elu
__global__ void dst_fused_kernel(const __half* __restrict__ wx16,
                                 const float* __restrict__ res,
                                 const float* __restrict__ sA, const float* __restrict__ sB,
                                 const float* __restrict__ relC, const int* __restrict__ off,
                                 const int* __restrict__ csr_src, const int* __restrict__ csr_et,
                                 float* __restrict__ hout, int N, int fin) {
    const int d = (blockIdx.x * blockDim.x + threadIdx.x) >> 5;
    if (d >= N) return;
    const int lane = threadIdx.x & 31;
    const int rs = off[d];
    const int re = off[d + 1];
    const float sAd = sA[d];

    float4 acc = make_float4(0.f, 0.f, 0.f, 0.f);
    float psum = 0.f;
    for (int j0 = rs; j0 < re; j0 += 32) {
        const int j = j0 + lane;
        float p = 0.f;
        int s = 0;
        if (j < re) {
            s = csr_src[j];
            const int t = csr_et[j];
            float sc = sAd + sB[s] + relC[t];
            sc = sc > 0.f ? sc : 0.2f * sc;
            p = __expf(sc);
        }
        psum += p;
        const int cnt = min(32, re - j0);
        for (int k = 0; k < cnt; k++) {
            const float pk = __shfl_sync(0xFFFFFFFFu, p, k);
            const int sk = __shfl_sync(0xFFFFFFFFu, s, k);
            // 8B load: 4 fp16 values per lane (row = 256 B total)
            const uint2 u = reinterpret_cast<const uint2*>(wx16 + (size_t)sk * 128)[lane];
            const float2 f0 = __half22float2(*reinterpret_cast<const __half2*>(&u.x));
            const float2 f1 = __half22float2(*reinterpret_cast<const __half2*>(&u.y));
            acc.x += f0.x * pk;
            acc.y += f0.y * pk;
            acc.z += f1.x * pk;
            acc.w += f1.y * pk;
        }
    }
#pragma unroll
    for (int o = 16; o; o >>= 1) psum += __shfl_xor_sync(0xFFFFFFFFu, psum, o);
    const float inv = psum > 0.f ? 1.f / psum : 0.f;

    const float4 r = reinterpret_cast<const float4*>(res + (size_t)d * 128)[lane];
    float4 v;
    v.x = acc.x * inv + r.x;
    v.y = acc.y * inv + r.y;
    v.z = acc.z * inv + r.z;
    v.w = acc.w * inv + r.w;
    v.x = v.x > 0.f ? v.x : expm1f(v.x);
    v.y = v.y > 0.f ? v.y : expm1f(v.y);
    v.z = v.z > 0.f ? v.z : expm1f(v.z);
    v.w = v.w > 0.f ? v.w : expm1f(v.w);
    if (fin) {
        float ss = v.x * v.x + v.y * v.y + v.z * v.z + v.w * v.w;
#pragma unroll
        for (int o = 16; o; o >>= 1) ss += __shfl_xor_sync(0xFFFFFFFFu, ss, o);
        const float nrm = 1.f / fmaxf(sqrtf(ss), 1e-12f);
        v.x *= nrm; v.y *= nrm; v.z *= nrm; v.w *= nrm;
    }
    reinterpret_cast<float4*>(hout + (size_t)d * 128)[lane] = v;
}

// ---------------- launch ----------------
extern "C" void kernel_launch(void* const* d_in, const int* in_sizes, int n_in,
                              void* d_out, int out_size) {
    const float* x = (const float*)d_in[0];
    const int* ei = (const int*)d_in[1];
    const int* et = (const int*)d_in[2];
    const float* l1W = (const float*)d_in[3];
    const float* l1b = (const float*)d_in[4];
    const float* l2W = (const float*)d_in[5];
    const float* l2b = (const float*)d_in[6];
    const float* W1 = (const float*)d_in[7];
    const float* Wr1 = (const float*)d_in[8];
    const float* a1 = (const float*)d_in[9];
    const float* Wres1 = (const float*)d_in[10];
    const float* rel1 = (const float*)d_in[11];
    const float* W2 = (const float*)d_in[12];
    const float* Wr2 = (const float*)d_in[13];
    const float* a2 = (const float*)d_in[14];
    const float* Wres2 = (const float*)d_in[15];
    const float* rel2 = (const float*)d_in[16];

    const int N = in_sizes[0] / IN_CH;
    const int E = in_sizes[2];
    const int* src = ei;
    const int* dst = ei + E;

    float *h, *agg, *sA, *sB, *relC;
    __half* wx16;
    int *cnt, *off, *cur, *csr_src, *csr_et;
    cudaGetSymbolAddress((void**)&h, g_h);
    cudaGetSymbolAddress((void**)&wx16, g_wx16);
    cudaGetSymbolAddress((void**)&agg, g_agg);
    cudaGetSymbolAddress((void**)&sA, g_sA);
    cudaGetSymbolAddress((void**)&sB, g_sB);
    cudaGetSymbolAddress((void**)&relC, g_relC);
    cudaGetSymbolAddress((void**)&cnt, g_cnt);
    cudaGetSymbolAddress((void**)&off, g_off);
    cudaGetSymbolAddress((void**)&cur, g_cur);
    cudaGetSymbolAddress((void**)&csr_src, g_csr_src);
    cudaGetSymbolAddress((void**)&csr_et, g_csr_et);

    const dim3 gGemm1(cdiv(N, 128), 1);
    const dim3 gGemm2(cdiv(N, 128), 2);
    const int gNodeWarp = cdiv(N, 8);
    const int gEdge = cdiv(E, 256);

    // CSR build (once per launch; graph shared by both layers)
    cudaMemsetAsync(cnt, 0, N * sizeof(int));
    count_kernel<<<gEdge, 256>>>(dst, cnt, E);
    scan_kernel<<<1, 1024>>>(cnt, off, cur, N, E);
    fill_kernel<<<gEdge, 256>>>(src, dst, et, cur, csr_src, csr_et, E);

    // layer 0: h = leaky_relu(x @ l1W^T + b, 0.01)
    gemm_mma<false><<<gGemm1, 256>>>(x, l1W, l1b, h, nullptr, nullptr, nullptr, nullptr,
                                     nullptr, nullptr, N, IN_CH, F_BIASLEAKY);

    const float* Ws[2] = {W1, W2};
    const float* Wrs[2] = {Wr1, Wr2};
    const float* as[2] = {a1, a2};
    const float* Wress[2] = {Wres1, Wres2};
    const float* rels[2] = {rel1, rel2};

    for (int l = 0; l < 2; l++) {
        relc_kernel<<<1, 1024>>>(Wrs[l], as[l], rels[l], relC);
        // y=0: wx16 = fp16(h@W^T) (+rowdot from fp32 acc); y=1: agg = h@Wres^T fp32
        gemm_mma<false><<<gGemm2, 256>>>(h, Ws[l], nullptr, nullptr, wx16, Wress[l], agg,
                                         as[l], sA, sB, N, HID, F_ROWDOT | F_C16);
        dst_fused_kernel<<<gNodeWarp, 256>>>(wx16, agg, sA, sB, relC, off, csr_src, csr_et,
                                             h, N, l == 1 ? 1 : 0);
    }

    // final: out = leaky_relu(h @ l2W^T + l2b, 0.01)
    gemm_mma<false><<<gGemm1, 256>>>(h, l2W, l2b, (float*)d_out, nullptr, nullptr, nullptr,
                                     nullptr, nullptr, nullptr, N, HID, F_BIASLEAKY);
}

// round 17
// speedup vs baseline: 1.8698x; 1.0755x over previous
#include <cuda_runtime.h>
#include <cuda_fp16.h>
#include <math.h>

// ---------------- problem constants ----------------
#define MAX_NODES 50000
#define MAX_EDGES 600000
#define IN_CH 768
#define HID 128
#define REL_DIM 200
#define NUM_RELS 5

// fp16 weight buffer offsets
#define W16_L1 0
#define W16_W1 (HID * IN_CH)
#define W16_WR1 (W16_W1 + HID * HID)
#define W16_W2 (W16_WR1 + HID * HID)
#define W16_WR2 (W16_W2 + HID * HID)
#define W16_L2 (W16_WR2 + HID * HID)
#define W16_TOTAL (W16_L2 + HID * HID)

// ---------------- scratch (device globals) ----------------
__device__ __half g_h16[MAX_NODES * HID];
__device__ __half g_wx16[MAX_NODES * HID];
__device__ float g_agg[MAX_NODES * HID];
__device__ __half g_w16[W16_TOTAL];
__device__ float g_sA[MAX_NODES];
__device__ float g_sB[MAX_NODES];
__device__ float g_relC[8];
__device__ int g_cnt[MAX_NODES];
__device__ int g_off[MAX_NODES + 1];
__device__ int g_cur[MAX_NODES];
__device__ int g_csr_src[MAX_EDGES];
__device__ int g_csr_et[MAX_EDGES];

static inline int cdiv(int a, int b) { return (a + b - 1) / b; }

__device__ __forceinline__ unsigned hpack(__half a, __half b) {
    unsigned short ua = *(unsigned short*)&a;
    unsigned short ub = *(unsigned short*)&b;
    return (unsigned)ua | ((unsigned)ub << 16);
}
__device__ __forceinline__ unsigned cvt2h(float x, float y) {
    return hpack(__float2half_rn(x), __float2half_rn(y));
}

// ---------------- batched fp32->fp16 weight convert (6 segments) ----------------
__global__ void cvtw6_kernel(const float* s0, const float* s1, const float* s2,
                             const float* s3, const float* s4, const float* s5,
                             __half* d0, __half* d1, __half* d2, __half* d3,
                             __half* d4, __half* d5, int n0, int nsmall) {
    const float* s;
    __half* d;
    int n4;
    switch (blockIdx.y) {
        case 0: s = s0; d = d0; n4 = n0; break;
        case 1: s = s1; d = d1; n4 = nsmall; break;
        case 2: s = s2; d = d2; n4 = nsmall; break;
        case 3: s = s3; d = d3; n4 = nsmall; break;
        case 4: s = s4; d = d4; n4 = nsmall; break;
        default: s = s5; d = d5; n4 = nsmall; break;
    }
    for (int i = blockIdx.x * blockDim.x + threadIdx.x; i < n4;
         i += gridDim.x * blockDim.x) {
        float4 v = reinterpret_cast<const float4*>(s)[i];
        reinterpret_cast<uint2*>(d)[i] = make_uint2(cvt2h(v.x, v.y), cvt2h(v.z, v.w));
    }
}

// ---------------- HMMA fp16 GEMM (R7-proven loop; operand types templated) -----
// C[M,128] = A[M,K] @ B[128,K]^T. AH/BH: operand already fp16 in global.
// fp32 operands are rounded to fp16 in regs during staging. fp32 accum.
// F_C16: write C as fp16. CTA 128x128, BK=32, 8 warps (2x4).
// blockIdx.y selects (B0,C0/Ch0,flags) or (B1,C1,0).
#define F_BIASLEAKY 1
#define F_ROWDOT 2
#define F_C16 4
#define GPAD 40

__device__ __forceinline__ void hmma16816(float* c, const unsigned* a, const unsigned* b) {
    asm volatile(
        "mma.sync.aligned.m16n8k16.row.col.f32.f16.f16.f32 "
        "{%0,%1,%2,%3}, {%4,%5,%6,%7}, {%8,%9}, {%0,%1,%2,%3};"
        : "+f"(c[0]), "+f"(c[1]), "+f"(c[2]), "+f"(c[3])
        : "r"(a[0]), "r"(a[1]), "r"(a[2]), "r"(a[3]), "r"(b[0]), "r"(b[1]));
}
__device__ __forceinline__ void ldmatrix_x4(unsigned& r0, unsigned& r1, unsigned& r2,
                                            unsigned& r3, unsigned addr) {
    asm volatile("ldmatrix.sync.aligned.m8n8.x4.shared.b16 {%0,%1,%2,%3}, [%4];"
                 : "=r"(r0), "=r"(r1), "=r"(r2), "=r"(r3)
                 : "r"(addr));
}

template <bool AH, bool BH>
__global__ __launch_bounds__(256, 2) void gemm_mma(
    const void* __restrict__ Av, const void* __restrict__ B0v,
    const float* __restrict__ bias, float* __restrict__ C0, __half* __restrict__ Ch0,
    const void* __restrict__ B1v, float* __restrict__ C1,
    const float* __restrict__ avec, float* __restrict__ sA, float* __restrict__ sB,
    int M, int K, int flags0) {
    __shared__ __align__(16) __half As16[128 * GPAD];
    __shared__ __align__(16) __half Bs16[128 * GPAD];
    __shared__ float s_red[2][128];

    const void* Bv = (blockIdx.y == 0) ? B0v : B1v;
    float* C = (blockIdx.y == 0) ? C0 : C1;
    const int flags = (blockIdx.y == 0) ? flags0 : 0;

    const int tid = threadIdx.x;
    const int wid = tid >> 5;
    const int lane = tid & 31;
    const int wm = wid & 1;
    const int wn = wid >> 1;
    const int m0 = blockIdx.x * 128;
    const int g = lane >> 2;
    const int tq = lane & 3;

    float acc[4][4][4];
#pragma unroll
    for (int i = 0; i < 4; i++)
#pragma unroll
        for (int j = 0; j < 4; j++)
#pragma unroll
            for (int k = 0; k < 4; k++) acc[i][j][k] = 0.f;

    // ldmatrix lane base addresses (R8-verified mapping)
    unsigned addrA[4], addrB[2];
    {
        const int rowa = (lane & 7) + ((lane >> 3) & 1) * 8;
        const int cola = (lane >> 4) * 8;
#pragma unroll
        for (int mt = 0; mt < 4; mt++) {
            const int r = wm * 64 + mt * 16 + rowa;
            addrA[mt] = (unsigned)__cvta_generic_to_shared(As16) +
                        (unsigned)((r * GPAD + cola) * 2);
        }
        const int rowb = (lane & 7) + (lane >> 4) * 8;
        const int colb = ((lane >> 3) & 1) * 8;
#pragma unroll
        for (int p = 0; p < 2; p++) {
            const int r = wn * 32 + p * 16 + rowb;
            addrB[p] = (unsigned)__cvta_generic_to_shared(Bs16) +
                       (unsigned)((r * GPAD + colb) * 2);
        }
    }

    const int lrow = tid >> 1;
    const int lc0 = (tid & 1) << 4;
    const int gr = m0 + lrow;
    const float* Af = (const float*)Av;
    const __half* Ah = (const __half*)Av;
    const float* Bf = (const float*)Bv;
    const __half* Bh = (const __half*)Bv;

    float4 avf[4], bvf[4];
    uint4 avh[2], bvh[2];

    auto load_tile = [&](int T) {
        const size_t ao = (size_t)gr * K + lc0 + (size_t)T * 32;
        const size_t bo = (size_t)lrow * K + lc0 + (size_t)T * 32;
        if (AH) {
            if (gr < M) {
                const uint4* p = reinterpret_cast<const uint4*>(Ah + ao);
                avh[0] = p[0];
                avh[1] = p[1];
            } else {
                avh[0] = make_uint4(0u, 0u, 0u, 0u);
                avh[1] = make_uint4(0u, 0u, 0u, 0u);
            }
        } else {
            const float4* p = reinterpret_cast<const float4*>(Af + ao);
#pragma unroll
            for (int q = 0; q < 4; q++)
                avf[q] = (gr < M) ? p[q] : make_float4(0.f, 0.f, 0.f, 0.f);
        }
        if (BH) {
            const uint4* p = reinterpret_cast<const uint4*>(Bh + bo);
            bvh[0] = p[0];
            bvh[1] = p[1];
        } else {
            const float4* p = reinterpret_cast<const float4*>(Bf + bo);
#pragma unroll
            for (int q = 0; q < 4; q++) bvf[q] = p[q];
        }
    };
    auto cvt_sts = [&]() {
        uint4* pa = reinterpret_cast<uint4*>(As16 + lrow * GPAD + lc0);
        if (AH) {
            pa[0] = avh[0];
            pa[1] = avh[1];
        } else {
            unsigned a8[8];
#pragma unroll
            for (int q = 0; q < 4; q++) {
                a8[q * 2] = cvt2h(avf[q].x, avf[q].y);
                a8[q * 2 + 1] = cvt2h(avf[q].z, avf[q].w);
            }
            pa[0] = make_uint4(a8[0], a8[1], a8[2], a8[3]);
            pa[1] = make_uint4(a8[4], a8[5], a8[6], a8[7]);
        }
        uint4* pb = reinterpret_cast<uint4*>(Bs16 + lrow * GPAD + lc0);
        if (BH) {
            pb[0] = bvh[0];
            pb[1] = bvh[1];
        } else {
            unsigned b8[8];
#pragma unroll
            for (int q = 0; q < 4; q++) {
                b8[q * 2] = cvt2h(bvf[q].x, bvf[q].y);
                b8[q * 2 + 1] = cvt2h(bvf[q].z, bvf[q].w);
            }
            pb[0] = make_uint4(b8[0], b8[1], b8[2], b8[3]);
            pb[1] = make_uint4(b8[4], b8[5], b8[6], b8[7]);
        }
    };

    const int nk = K >> 5;
    load_tile(0);
    for (int it = 0; it < nk; it++) {
        __syncthreads();  // all warps done with smem from prev iter
        cvt_sts();
        __syncthreads();
        if (it + 1 < nk) load_tile(it + 1);  // overlaps with MMA below
#pragma unroll
        for (int ks = 0; ks < 2; ks++) {
            const unsigned koff = (unsigned)(ks * 32);
            unsigned a[4][4], b[4][2];
#pragma unroll
            for (int mt = 0; mt < 4; mt++)
                ldmatrix_x4(a[mt][0], a[mt][1], a[mt][2], a[mt][3], addrA[mt] + koff);
#pragma unroll
            for (int p = 0; p < 2; p++)
                ldmatrix_x4(b[p * 2][0], b[p * 2][1], b[p * 2 + 1][0], b[p * 2 + 1][1],
                            addrB[p] + koff);
#pragma unroll
            for (int mt = 0; mt < 4; mt++)
#pragma unroll
                for (int nt = 0; nt < 4; nt++) hmma16816(acc[mt][nt], a[mt], b[nt]);
        }
    }

    // ---------------- epilogue ----------------
    const bool dorow = (flags & F_ROWDOT) != 0;
    if (dorow) {
        if (tid < 128) { s_red[0][tid] = 0.f; s_red[1][tid] = 0.f; }
        __syncthreads();
    }
#pragma unroll
    for (int mt = 0; mt < 4; mt++) {
        float pa[2] = {0.f, 0.f}, pb[2] = {0.f, 0.f};
#pragma unroll
        for (int nt = 0; nt < 4; nt++) {
            const int c = wn * 32 + nt * 8 + tq * 2;
            float bi0 = 0.f, bi1 = 0.f;
            if (flags & F_BIASLEAKY) { bi0 = bias[c]; bi1 = bias[c + 1]; }
            float aA0 = 0.f, aA1 = 0.f, aB0 = 0.f, aB1 = 0.f;
            if (dorow) {
                aA0 = avec[c]; aA1 = avec[c + 1];
                aB0 = avec[128 + c]; aB1 = avec[128 + c + 1];
            }
#pragma unroll
            for (int half = 0; half < 2; half++) {
                const int r = m0 + wm * 64 + mt * 16 + g + half * 8;
                float v0 = acc[mt][nt][half * 2 + 0];
                float v1 = acc[mt][nt][half * 2 + 1];
                if (flags & F_BIASLEAKY) {
                    v0 += bi0; v1 += bi1;
                    v0 = v0 > 0.f ? v0 : 0.01f * v0;
                    v1 = v1 > 0.f ? v1 : 0.01f * v1;
                }
                if (dorow) {
                    pa[half] += v0 * aA0 + v1 * aA1;
                    pb[half] += v0 * aB0 + v1 * aB1;
                }
                if (r < M) {
                    if (flags & F_C16)
                        *reinterpret_cast<unsigned*>(Ch0 + (size_t)r * 128 + c) = cvt2h(v0, v1);
                    else
                        *reinterpret_cast<float2*>(C + (size_t)r * 128 + c) = make_float2(v0, v1);
                }
            }
        }
        if (dorow) {
#pragma unroll
            for (int half = 0; half < 2; half++) {
                const int lr = wm * 64 + mt * 16 + g + half * 8;
                atomicAdd(&s_red[0][lr], pa[half]);
                atomicAdd(&s_red[1][lr], pb[half]);
            }
        }
    }
    if (dorow) {
        __syncthreads();
        if (tid < 128 && m0 + tid < M) {
            sA[m0 + tid] = s_red[0][tid];
            sB[m0 + tid] = s_red[1][tid];
        }
    }
}

// ---------------- relC[r] = (rel[r] @ Wr^T) . aC ----------------
__global__ __launch_bounds__(1024) void relc_kernel(const float* __restrict__ Wr,
                                                    const float* __restrict__ a,
                                                    const float* __restrict__ rel,
                                                    float* __restrict__ relC) {
    __shared__ float part[4 * REL_DIM];
    __shared__ float v[REL_DIM];
    const int tid = threadIdx.x;
    const int t = tid & 255;
    const int p = tid >> 8;
    if (t < REL_DIM) {
        float s = 0.f;
        const int h0 = p * 32;
#pragma unroll 8
        for (int h = 0; h < 32; h++) s += a[2 * HID + h0 + h] * Wr[(size_t)(h0 + h) * REL_DIM + t];
        part[p * REL_DIM + t] = s;
    }
    __syncthreads();
    if (tid < REL_DIM)
        v[tid] = part[tid] + part[REL_DIM + tid] + part[2 * REL_DIM + tid] + part[3 * REL_DIM + tid];
    __syncthreads();
    const int r = tid >> 5;
    const int lane = tid & 31;
    if (r < NUM_RELS) {
        float s = 0.f;
        for (int k = lane; k < REL_DIM; k += 32) s += rel[r * REL_DIM + k] * v[k];
#pragma unroll
        for (int o = 16; o; o >>= 1) s += __shfl_xor_sync(0xFFFFFFFFu, s, o);
        if (lane == 0) relC[r] = s;
    }
}

// ---------------- CSR build (by dst) ----------------
__global__ void count_kernel(const int* __restrict__ dst, int* __restrict__ cnt, int E) {
    const int e = blockIdx.x * blockDim.x + threadIdx.x;
    if (e < E) atomicAdd(cnt + dst[e], 1);
}

__global__ __launch_bounds__(1024) void scan_kernel(const int* __restrict__ cnt,
                                                    int* __restrict__ off,
                                                    int* __restrict__ cur, int N, int E) {
    __shared__ int part[1024];
    const int tid = threadIdx.x;
    const int chunk = (N + 1023) >> 10;
    const int s0 = tid * chunk;
    int s = 0;
    for (int i = 0; i < chunk; i++) {
        const int idx = s0 + i;
        if (idx < N) s += cnt[idx];
    }
    part[tid] = s;
    __syncthreads();
    for (int o = 1; o < 1024; o <<= 1) {
        int t = (tid >= o) ? part[tid - o] : 0;
        __syncthreads();
        part[tid] += t;
        __syncthreads();
    }
    int run = part[tid] - s;  // exclusive base
    for (int i = 0; i < chunk; i++) {
        const int idx = s0 + i;
        if (idx < N) {
            off[idx] = run;
            cur[idx] = run;
            run += cnt[idx];
        }
    }
    if (tid == 0) off[N] = E;
}

__global__ void fill_kernel(const int* __restrict__ src, const int* __restrict__ dst,
                            const int* __restrict__ et, int* __restrict__ cur,
                            int* __restrict__ csr_src, int* __restrict__ csr_et, int E) {
    const int e = blockIdx.x * blockDim.x + threadIdx.x;
    if (e >= E) return;
    const int pos = atomicAdd(cur + dst[e], 1);
    csr_src[pos] = src[e];
    csr_et[pos] = et[e];
}

// ---------------- fused per-dst attention (wx fp16): softmax + agg + residual + elu
__global__ void dst_fused_kernel(const __half* __restrict__ wx16,
                                 const float* __restrict__ res,
                                 const float* __restrict__ sA, const float* __restrict__ sB,
                                 const float* __restrict__ relC, const int* __restrict__ off,
                                 const int* __restrict__ csr_src, const int* __restrict__ csr_et,
                                 __half* __restrict__ hout16, int N, int fin) {
    const int d = (blockIdx.x * blockDim.x + threadIdx.x) >> 5;
    if (d >= N) return;
    const int lane = threadIdx.x & 31;
    const int rs = off[d];
    const int re = off[d + 1];
    const float sAd = sA[d];

    float4 acc = make_float4(0.f, 0.f, 0.f, 0.f);
    float psum = 0.f;
    for (int j0 = rs; j0 < re; j0 += 32) {
        const int j = j0 + lane;
        float p = 0.f;
        int s = 0;
        if (j < re) {
            s = csr_src[j];
            const int t = csr_et[j];
            float sc = sAd + sB[s] + relC[t];
            sc = sc > 0.f ? sc : 0.2f * sc;
            p = __expf(sc);
        }
        psum += p;
        const int cnt = min(32, re - j0);
        for (int k = 0; k < cnt; k++) {
            const float pk = __shfl_sync(0xFFFFFFFFu, p, k);
            const int sk = __shfl_sync(0xFFFFFFFFu, s, k);
            const uint2 u = reinterpret_cast<const uint2*>(wx16 + (size_t)sk * 128)[lane];
            const float2 f0 = __half22float2(*reinterpret_cast<const __half2*>(&u.x));
            const float2 f1 = __half22float2(*reinterpret_cast<const __half2*>(&u.y));
            acc.x += f0.x * pk;
            acc.y += f0.y * pk;
            acc.z += f1.x * pk;
            acc.w += f1.y * pk;
        }
    }
#pragma unroll
    for (int o = 16; o; o >>= 1) psum += __shfl_xor_sync(0xFFFFFFFFu, psum, o);
    const float inv = psum > 0.f ? 1.f / psum : 0.f;

    const float4 r = reinterpret_cast<const float4*>(res + (size_t)d * 128)[lane];
    float4 v;
    v.x = acc.x * inv + r.x;
    v.y = acc.y * inv + r.y;
    v.z = acc.z * inv + r.z;
    v.w = acc.w * inv + r.w;
    v.x = v.x > 0.f ? v.x : expm1f(v.x);
    v.y = v.y > 0.f ? v.y : expm1f(v.y);
    v.z = v.z > 0.f ? v.z : expm1f(v.z);
    v.w = v.w > 0.f ? v.w : expm1f(v.w);
    if (fin) {
        float ss = v.x * v.x + v.y * v.y + v.z * v.z + v.w * v.w;
#pragma unroll
        for (int o = 16; o; o >>= 1) ss += __shfl_xor_sync(0xFFFFFFFFu, ss, o);
        const float nrm = 1.f / fmaxf(sqrtf(ss), 1e-12f);
        v.x *= nrm; v.y *= nrm; v.z *= nrm; v.w *= nrm;
    }
    reinterpret_cast<uint2*>(hout16 + (size_t)d * 128)[lane] =
        make_uint2(cvt2h(v.x, v.y), cvt2h(v.z, v.w));
}

// ---------------- launch ----------------
extern "C" void kernel_launch(void* const* d_in, const int* in_sizes, int n_in,
                              void* d_out, int out_size) {
    const float* x = (const float*)d_in[0];
    const int* ei = (const int*)d_in[1];
    const int* et = (const int*)d_in[2];
    const float* l1W = (const float*)d_in[3];
    const float* l1b = (const float*)d_in[4];
    const float* l2W = (const float*)d_in[5];
    const float* l2b = (const float*)d_in[6];
    const float* W1 = (const float*)d_in[7];
    const float* Wr1 = (const float*)d_in[8];
    const float* a1 = (const float*)d_in[9];
    const float* Wres1 = (const float*)d_in[10];
    const float* rel1 = (const float*)d_in[11];
    const float* W2 = (const float*)d_in[12];
    const float* Wr2 = (const float*)d_in[13];
    const float* a2 = (const float*)d_in[14];
    const float* Wres2 = (const float*)d_in[15];
    const float* rel2 = (const float*)d_in[16];

    const int N = in_sizes[0] / IN_CH;
    const int E = in_sizes[2];
    const int* src = ei;
    const int* dst = ei + E;

    float *agg, *sA, *sB, *relC;
    __half *h16, *wx16, *w16;
    int *cnt, *off, *cur, *csr_src, *csr_et;
    cudaGetSymbolAddress((void**)&h16, g_h16);
    cudaGetSymbolAddress((void**)&wx16, g_wx16);
    cudaGetSymbolAddress((void**)&agg, g_agg);
    cudaGetSymbolAddress((void**)&w16, g_w16);
    cudaGetSymbolAddress((void**)&sA, g_sA);
    cudaGetSymbolAddress((void**)&sB, g_sB);
    cudaGetSymbolAddress((void**)&relC, g_relC);
    cudaGetSymbolAddress((void**)&cnt, g_cnt);
    cudaGetSymbolAddress((void**)&off, g_off);
    cudaGetSymbolAddress((void**)&cur, g_cur);
    cudaGetSymbolAddress((void**)&csr_src, g_csr_src);
    cudaGetSymbolAddress((void**)&csr_et, g_csr_et);

    const dim3 gGemm1(cdiv(N, 128), 1);
    const dim3 gGemm2(cdiv(N, 128), 2);
    const int gNodeWarp = cdiv(N, 8);
    const int gEdge = cdiv(E, 256);

    // weight fp16 pre-convert (once)
    cvtw6_kernel<<<dim3(96, 6), 256>>>(
        l1W, W1, Wres1, W2, Wres2, l2W,
        w16 + W16_L1, w16 + W16_W1, w16 + W16_WR1, w16 + W16_W2, w16 + W16_WR2,
        w16 + W16_L2, HID * IN_CH / 4, HID * HID / 4);

    // CSR build (once; graph shared by both layers)
    cudaMemsetAsync(cnt, 0, N * sizeof(int));
    count_kernel<<<gEdge, 256>>>(dst, cnt, E);
    scan_kernel<<<1, 1024>>>(cnt, off, cur, N, E);
    fill_kernel<<<gEdge, 256>>>(src, dst, et, cur, csr_src, csr_et, E);

    // layer 0: h16 = fp16(leaky_relu(x @ l1W^T + b, 0.01))
    gemm_mma<false, true><<<gGemm1, 256>>>(x, w16 + W16_L1, l1b, nullptr, h16, nullptr,
                                           nullptr, nullptr, nullptr, nullptr, N, IN_CH,
                                           F_BIASLEAKY | F_C16);

    const float* Wrs[2] = {Wr1, Wr2};
    const float* as[2] = {a1, a2};
    const float* rels[2] = {rel1, rel2};
    const int wofs[2] = {W16_W1, W16_W2};
    const int wrofs[2] = {W16_WR1, W16_WR2};

    for (int l = 0; l < 2; l++) {
        relc_kernel<<<1, 1024>>>(Wrs[l], as[l], rels[l], relC);
        // y=0: wx16 = fp16(h@W^T) (+rowdot); y=1: agg = h@Wres^T fp32
        gemm_mma<true, true><<<gGemm2, 256>>>(h16, w16 + wofs[l], nullptr, nullptr, wx16,
                                              w16 + wrofs[l], agg, as[l], sA, sB, N, HID,
                                              F_ROWDOT | F_C16);
        dst_fused_kernel<<<gNodeWarp, 256>>>(wx16, agg, sA, sB, relC, off, csr_src, csr_et,
                                             h16, N, l == 1 ? 1 : 0);
    }

    // final: out = leaky_relu(h @ l2W^T + l2b, 0.01)
    gemm_mma<true, true><<<gGemm1, 256>>>(h16, w16 + W16_L2, l2b, (float*)d_out, nullptr,
                                          nullptr, nullptr, nullptr, nullptr, nullptr, N,
                                          HID, F_BIASLEAKY);
}